// round 7
// baseline (speedup 1.0000x reference)
#include <cuda_runtime.h>

// ---------------------------------------------------------------------------
// FeatureExtractorViT  (B=512, C=3, IMG=36, PS=6, S=36, D=768, H=12, HD=64,
//                       L=4, OUT=256)
// Token count NT = B*C*S = 55296.  All math fp32 (rel_err target 1e-3).
// ---------------------------------------------------------------------------

#define NT    55296      // B*C*S tokens
#define DD    768
#define NBC   1536       // B*C sequences
#define SS    36
#define NH    12
#define HDIM  64
#define NL    4
#define DOUT  256
#define DMLP  1536

// Scratch (device globals — allocation inside kernel_launch is forbidden)
static __device__ float g_z[NT * DD];     // residual stream
static __device__ float g_h[NT * DD];     // layernorm output
static __device__ float g_q[NT * DD];
static __device__ float g_k[NT * DD];
static __device__ float g_v[NT * DD];
static __device__ float g_m[NT * DMLP];   // MLP hidden

// ---------------------------------------------------------------------------
// 1) Patch embed: z[bc,s,d] = sum_p pixel[bc,s,p]*Wp[d,p] + bp[d] + pos[s,d]
//    grid (6, 1536), block 128: each block = 128 d-channels for one sequence.
// ---------------------------------------------------------------------------
__global__ void patch_embed_kernel(const float* __restrict__ batch,
                                   const float* __restrict__ Wp,
                                   const float* __restrict__ bp,
                                   const float* __restrict__ pos)
{
    __shared__ float px[36 * 36];     // [s][p]
    __shared__ float Ws[128 * 36];    // [d_local][p]
    const int bc = blockIdx.y;
    const int d0 = blockIdx.x * 128;
    const int t  = threadIdx.x;

    const float* img = batch + bc * 1296;
    for (int e = t; e < 1296; e += 128) {
        int row = e / 36, col = e - row * 36;
        int s = (row / 6) * 6 + (col / 6);
        int p = (row % 6) * 6 + (col % 6);
        px[s * 36 + p] = img[e];
    }
    for (int i = t; i < 128 * 36; i += 128)
        Ws[i] = Wp[d0 * 36 + i];
    __syncthreads();

    const int d = d0 + t;
    float w[36];
#pragma unroll
    for (int p = 0; p < 36; p++) w[p] = Ws[t * 36 + p];
    const float bias = bp[d];

    for (int s = 0; s < 36; s++) {
        float acc = bias + pos[s * 768 + d];
        const float* pr = &px[s * 36];
#pragma unroll
        for (int p = 0; p < 36; p++) acc = fmaf(pr[p], w[p], acc);
        g_z[(bc * 36 + s) * 768 + d] = acc;
    }
}

// ---------------------------------------------------------------------------
// 2) LayerNorm: one block (256 threads) per token row of 768.
// ---------------------------------------------------------------------------
__global__ void ln_kernel(const float* __restrict__ in, float* __restrict__ out,
                          const float* __restrict__ gamma,
                          const float* __restrict__ beta)
{
    const int row = blockIdx.x;
    const float* x = in + (size_t)row * 768;
    const int t = threadIdx.x;
    float v0 = x[t], v1 = x[t + 256], v2 = x[t + 512];
    float s = v0 + v1 + v2;
    float q = v0 * v0 + v1 * v1 + v2 * v2;
#pragma unroll
    for (int o = 16; o > 0; o >>= 1) {
        s += __shfl_xor_sync(0xffffffffu, s, o);
        q += __shfl_xor_sync(0xffffffffu, q, o);
    }
    __shared__ float rs[8], rq[8];
    __shared__ float smean, srstd;
    if ((t & 31) == 0) { rs[t >> 5] = s; rq[t >> 5] = q; }
    __syncthreads();
    if (t == 0) {
        float S = 0.f, Q = 0.f;
#pragma unroll
        for (int i = 0; i < 8; i++) { S += rs[i]; Q += rq[i]; }
        float m   = S * (1.0f / 768.0f);
        float var = Q * (1.0f / 768.0f) - m * m;
        smean = m;
        srstd = rsqrtf(var + 1e-5f);
    }
    __syncthreads();
    const float m = smean, r = srstd;
    float* o = out + (size_t)row * 768;
    o[t]       = (v0 - m) * r * gamma[t]       + beta[t];
    o[t + 256] = (v1 - m) * r * gamma[t + 256] + beta[t + 256];
    o[t + 512] = (v2 - m) * r * gamma[t + 512] + beta[t + 512];
}

// ---------------------------------------------------------------------------
// 3) Per-head QKV: q[tok,h,e] = sum_d h[tok,h,d]*Wq[h,e,d] + bq[h,e]
//    grid (NT/64, 12), block 256: 64-token x 64-e tile, loop over {q,k,v}.
// ---------------------------------------------------------------------------
__global__ void __launch_bounds__(256)
qkv_kernel(const float* __restrict__ Wq, const float* __restrict__ bq,
           const float* __restrict__ Wk, const float* __restrict__ bk,
           const float* __restrict__ Wv, const float* __restrict__ bv)
{
    __shared__ float Hs[64 * 65];   // [tok][d], padded
    __shared__ float Ws[64 * 65];   // [d][e],   padded
    __shared__ float bs[64];
    const int m0 = blockIdx.x * 64;
    const int h  = blockIdx.y;
    const int t  = threadIdx.x;

    for (int idx = t; idx < 4096; idx += 256) {
        int tok = idx >> 6, e = idx & 63;
        Hs[tok * 65 + e] = g_h[(size_t)(m0 + tok) * 768 + h * 64 + e];
    }
    const float* Wlist[3] = { Wq + h * 4096, Wk + h * 4096, Wv + h * 4096 };
    const float* blist[3] = { bq + h * 64,   bk + h * 64,   bv + h * 64 };
    float* olist[3] = { g_q, g_k, g_v };
    const int tx = t & 15, ty = t >> 4;

#pragma unroll
    for (int w = 0; w < 3; w++) {
        __syncthreads();   // previous compute done before overwriting Ws
        const float* W = Wlist[w];
        for (int idx = t; idx < 4096; idx += 256) {
            int e = idx >> 6, d = idx & 63;
            Ws[d * 65 + e] = W[idx];
        }
        if (t < 64) bs[t] = blist[w][t];
        __syncthreads();

        float acc[4][4] = {};
        for (int d = 0; d < 64; d++) {
            float a[4], b[4];
#pragma unroll
            for (int i = 0; i < 4; i++) a[i] = Hs[(ty * 4 + i) * 65 + d];
#pragma unroll
            for (int j = 0; j < 4; j++) b[j] = Ws[d * 65 + tx * 4 + j];
#pragma unroll
            for (int i = 0; i < 4; i++)
#pragma unroll
                for (int j = 0; j < 4; j++)
                    acc[i][j] = fmaf(a[i], b[j], acc[i][j]);
        }
        float* o = olist[w];
#pragma unroll
        for (int i = 0; i < 4; i++)
#pragma unroll
            for (int j = 0; j < 4; j++)
                o[(size_t)(m0 + ty * 4 + i) * 768 + h * 64 + tx * 4 + j] =
                    acc[i][j] + bs[tx * 4 + j];
    }
}

// ---------------------------------------------------------------------------
// 4) Attention per (sequence, head): 36x36 scores, softmax, @V, residual add.
//    grid (1536, 12), block 256.
// ---------------------------------------------------------------------------
__global__ void __launch_bounds__(256) attn_kernel()
{
    __shared__ float Qs[36 * 65], Ks[36 * 65], Vs[36 * 65];
    __shared__ float P[36 * 40];
    const int bc = blockIdx.x, h = blockIdx.y;
    const int t = threadIdx.x;
    const size_t base = (size_t)bc * 36 * 768 + h * 64;

    for (int idx = t; idx < 2304; idx += 256) {
        int s_ = idx >> 6, e = idx & 63;
        size_t gi = base + (size_t)s_ * 768 + e;
        Qs[s_ * 65 + e] = g_q[gi];
        Ks[s_ * 65 + e] = g_k[gi];
        Vs[s_ * 65 + e] = g_v[gi];
    }
    __syncthreads();

    for (int sc = t; sc < 1296; sc += 256) {
        int i = sc / 36, j = sc - i * 36;
        float a = 0.f;
        const float* qi = &Qs[i * 65];
        const float* kj = &Ks[j * 65];
#pragma unroll
        for (int e = 0; e < 64; e++) a = fmaf(qi[e], kj[e], a);
        P[i * 40 + j] = a * 0.125f;   // 1/sqrt(64)
    }
    __syncthreads();

    if (t < 36) {
        float mx = -1e30f;
        for (int j = 0; j < 36; j++) mx = fmaxf(mx, P[t * 40 + j]);
        float sum = 0.f;
        for (int j = 0; j < 36; j++) {
            float ex = expf(P[t * 40 + j] - mx);
            P[t * 40 + j] = ex;
            sum += ex;
        }
        float inv = 1.f / sum;
        for (int j = 0; j < 36; j++) P[t * 40 + j] *= inv;
    }
    __syncthreads();

    for (int oi = t; oi < 2304; oi += 256) {
        int i = oi >> 6, e = oi & 63;
        float acc = 0.f;
        const float* pi = &P[i * 40];
#pragma unroll
        for (int j = 0; j < 36; j++) acc = fmaf(pi[j], Vs[j * 65 + e], acc);
        g_z[base + (size_t)i * 768 + e] += acc;   // residual, unique per (bc,h,e)
    }
}

// ---------------------------------------------------------------------------
// 5) SGEMM: C[M,N] = A[M,K] @ B[N,K]^T + bias[N]  (+ReLU) (+res[M,N])
//    128x128 tile, BK=8, 256 threads, 8x8 microtile, register prefetch.
// ---------------------------------------------------------------------------
template <bool RELU, bool RES>
__global__ void __launch_bounds__(256)
sgemm_tn(const float* __restrict__ A, const float* __restrict__ B,
         const float* __restrict__ bias, const float* __restrict__ res,
         float* __restrict__ C, int M, int N, int K)
{
    __shared__ float As[8][128];
    __shared__ float Bs[8][128];
    const int t  = threadIdx.x;
    const int n0 = blockIdx.x * 128;
    const int m0 = blockIdx.y * 128;
    const int lr = t >> 1;            // tile row 0..127
    const int lc = (t & 1) * 4;       // k offset 0 / 4
    const float* Aptr = A + (size_t)(m0 + lr) * K + lc;
    const float* Bptr = B + (size_t)(n0 + lr) * K + lc;
    const int tx = t & 15, ty = t >> 4;

    float acc[8][8] = {};
    float4 ra = *(const float4*)Aptr;
    float4 rb = *(const float4*)Bptr;
    const int NK = K >> 3;

    for (int ks = 0; ks < NK; ks++) {
        As[lc + 0][lr] = ra.x; As[lc + 1][lr] = ra.y;
        As[lc + 2][lr] = ra.z; As[lc + 3][lr] = ra.w;
        Bs[lc + 0][lr] = rb.x; Bs[lc + 1][lr] = rb.y;
        Bs[lc + 2][lr] = rb.z; Bs[lc + 3][lr] = rb.w;
        __syncthreads();
        if (ks + 1 < NK) {             // prefetch next tile into registers
            ra = *(const float4*)(Aptr + (ks + 1) * 8);
            rb = *(const float4*)(Bptr + (ks + 1) * 8);
        }
#pragma unroll
        for (int k = 0; k < 8; k++) {
            float a[8], b[8];
            *(float4*)&a[0] = *(const float4*)&As[k][ty * 8];
            *(float4*)&a[4] = *(const float4*)&As[k][ty * 8 + 4];
            *(float4*)&b[0] = *(const float4*)&Bs[k][tx * 8];
            *(float4*)&b[4] = *(const float4*)&Bs[k][tx * 8 + 4];
#pragma unroll
            for (int i = 0; i < 8; i++)
#pragma unroll
                for (int j = 0; j < 8; j++)
                    acc[i][j] = fmaf(a[i], b[j], acc[i][j]);
        }
        __syncthreads();
    }

    float bv[8];
    *(float4*)&bv[0] = *(const float4*)&bias[n0 + tx * 8];
    *(float4*)&bv[4] = *(const float4*)&bias[n0 + tx * 8 + 4];
#pragma unroll
    for (int i = 0; i < 8; i++) {
        const int row = m0 + ty * 8 + i;
        const size_t off = (size_t)row * N + n0 + tx * 8;
        float v[8];
#pragma unroll
        for (int j = 0; j < 8; j++) {
            float x = acc[i][j] + bv[j];
            if (RELU) x = fmaxf(x, 0.f);
            v[j] = x;
        }
        if (RES) {
            float4 r0 = *(const float4*)&res[off];
            float4 r1 = *(const float4*)&res[off + 4];
            v[0] += r0.x; v[1] += r0.y; v[2] += r0.z; v[3] += r0.w;
            v[4] += r1.x; v[5] += r1.y; v[6] += r1.z; v[7] += r1.w;
        }
        *(float4*)&C[off]     = make_float4(v[0], v[1], v[2], v[3]);
        *(float4*)&C[off + 4] = make_float4(v[4], v[5], v[6], v[7]);
    }
}

// ---------------------------------------------------------------------------
// Launch
// ---------------------------------------------------------------------------
extern "C" void kernel_launch(void* const* d_in, const int* in_sizes, int n_in,
                              void* d_out, int out_size)
{
    (void)in_sizes; (void)n_in; (void)out_size;
    const float* batch = (const float*)d_in[0];
    const float* Wp    = (const float*)d_in[1];
    const float* bp    = (const float*)d_in[2];
    const float* pos   = (const float*)d_in[3];
    const float* ln1g  = (const float*)d_in[4];
    const float* ln1b  = (const float*)d_in[5];
    const float* Wq    = (const float*)d_in[6];
    const float* bq    = (const float*)d_in[7];
    const float* Wk    = (const float*)d_in[8];
    const float* bk    = (const float*)d_in[9];
    const float* Wv    = (const float*)d_in[10];
    const float* bv    = (const float*)d_in[11];
    const float* ln2g  = (const float*)d_in[12];
    const float* ln2b  = (const float*)d_in[13];
    const float* W1    = (const float*)d_in[14];
    const float* b1    = (const float*)d_in[15];
    const float* W2    = (const float*)d_in[16];
    const float* b2    = (const float*)d_in[17];
    const float* Wout  = (const float*)d_in[18];
    const float* bout  = (const float*)d_in[19];

    float *zp = nullptr, *hp = nullptr, *mp = nullptr;
    cudaGetSymbolAddress((void**)&zp, g_z);
    cudaGetSymbolAddress((void**)&hp, g_h);
    cudaGetSymbolAddress((void**)&mp, g_m);

    patch_embed_kernel<<<dim3(6, NBC), 128>>>(batch, Wp, bp, pos);

    for (int l = 0; l < NL; l++) {
        ln_kernel<<<NT, 256>>>(zp, hp, ln1g + l * 768, ln1b + l * 768);
        qkv_kernel<<<dim3(NT / 64, NH), 256>>>(
            Wq + l * NH * 4096, bq + l * NH * 64,
            Wk + l * NH * 4096, bk + l * NH * 64,
            Wv + l * NH * 4096, bv + l * NH * 64);
        attn_kernel<<<dim3(NBC, NH), 256>>>();
        ln_kernel<<<NT, 256>>>(zp, hp, ln2g + l * 768, ln2b + l * 768);
        sgemm_tn<true,  false><<<dim3(DMLP / 128, NT / 128), 256>>>(
            hp, W1 + (size_t)l * DMLP * DD, b1 + l * DMLP, nullptr, mp,
            NT, DMLP, DD);
        sgemm_tn<false, true><<<dim3(DD / 128, NT / 128), 256>>>(
            mp, W2 + (size_t)l * DD * DMLP, b2 + l * DD, hp, zp,
            NT, DD, DMLP);
    }

    sgemm_tn<false, false><<<dim3(DOUT / 128, NT / 128), 256>>>(
        zp, Wout, bout, nullptr, (float*)d_out, NT, DOUT, DD);
}

// round 10
// speedup vs baseline: 1.9190x; 1.9190x over previous
#include <cuda_runtime.h>
#include <cuda_bf16.h>
#include <cstdint>

// ---------------------------------------------------------------------------
// FeatureExtractorViT (B=512,C=3,IMG=36,PS=6,S=36,D=768,H=12,HD=64,L=4,OUT=256)
// NT = 55296 tokens.  GEMMs via mma.sync bf16 (HMMA, plain-sm_103-legal) with
// split-bf16 3-pass accumulation (fp32-grade).  hi/lo splits precomputed.
// ---------------------------------------------------------------------------

#define NT    55296
#define DD    768
#define NBC   1536
#define NH    12
#define NL    4
#define DOUT  256
#define DMLP  1536
#define NQKV  2304

// GEMM tiling
#define BM 256
#define BN 128
#define BK 32              // fp32 k per chunk (bf16 cols: hi 0..31, lo 32..63)
#define KS 72              // smem row stride in bf16 (144 B, conflict-free)
#define ASZ (BM * KS * 2)  // bytes per A buffer
#define BSZ (BN * KS * 2)
#define SMEM_BYTES (2 * ASZ + 2 * BSZ)   // 110592

// ---------------- scratch (device globals; no runtime alloc) ---------------
static __device__ float    g_z[(size_t)NT * DD];       // residual stream (fp32)
static __device__ float    g_qkv[(size_t)NT * NQKV];   // q|k|v (fp32)
static __device__ uint16_t g_hh[(size_t)NT * DD];      // LN out hi (bf16 bits)
static __device__ uint16_t g_hl[(size_t)NT * DD];      // LN out lo
static __device__ uint16_t g_mh[(size_t)NT * DMLP];    // MLP hidden hi
static __device__ uint16_t g_ml[(size_t)NT * DMLP];    // MLP hidden lo
static __device__ uint16_t g_w1h[(size_t)NL * DMLP * DD], g_w1l[(size_t)NL * DMLP * DD];
static __device__ uint16_t g_w2h[(size_t)NL * DD * DMLP], g_w2l[(size_t)NL * DD * DMLP];
static __device__ uint16_t g_wqh[(size_t)NL * NQKV * 128], g_wql[(size_t)NL * NQKV * 128];
static __device__ uint16_t g_woh[(size_t)DOUT * DD], g_wol[(size_t)DOUT * DD];
static __device__ float    g_bp[(size_t)NL * NQKV];

// ---------------------------- helpers --------------------------------------
__device__ __forceinline__ uint32_t smem_u32(const void* p) {
    uint32_t a;
    asm("{ .reg .u64 t; cvta.to.shared.u64 t, %1; cvt.u32.u64 %0, t; }"
        : "=r"(a) : "l"(p));
    return a;
}
__device__ __forceinline__ uint32_t lds32(uint32_t a) {
    uint32_t v;
    asm("ld.shared.b32 %0, [%1];" : "=r"(v) : "r"(a));
    return v;
}
__device__ __forceinline__ float bf2f(uint16_t b) {
    return __uint_as_float((uint32_t)b << 16);
}
__device__ __forceinline__ void split1(float x, uint16_t& h, uint16_t& l) {
    __nv_bfloat16 hb = __float2bfloat16_rn(x);
    h = __bfloat16_as_ushort(hb);
    l = __bfloat16_as_ushort(__float2bfloat16_rn(x - __bfloat162float(hb)));
}
__device__ __forceinline__ void mma16816(float& d0, float& d1, float& d2, float& d3,
                                         uint32_t a0, uint32_t a1, uint32_t a2,
                                         uint32_t a3, uint32_t b0, uint32_t b1) {
    asm("mma.sync.aligned.m16n8k16.row.col.f32.bf16.bf16.f32 "
        "{%0,%1,%2,%3}, {%4,%5,%6,%7}, {%8,%9}, {%0,%1,%2,%3};"
        : "+f"(d0), "+f"(d1), "+f"(d2), "+f"(d3)
        : "r"(a0), "r"(a1), "r"(a2), "r"(a3), "r"(b0), "r"(b1));
}
#define CP16(dst, src) \
    asm volatile("cp.async.ca.shared.global [%0], [%1], 16;" :: "r"(dst), "l"(src))
#define CP_COMMIT() asm volatile("cp.async.commit_group;" ::: "memory")
#define CP_WAIT(n)  asm volatile("cp.async.wait_group %0;" :: "n"(n) : "memory")

// ---------------------- GEMM: C = A @ B^T (+bias,+relu,+res) ---------------
// A: [M,K] as hi/lo bf16 (lda);  B: [N,K] hi/lo bf16 (ldb).
// C = Ah*Bh + Ah*Bl + Al*Bh, fp32 accumulate.  Tile 256x128, 8 warps (4x2),
// warp tile 64x64 (m16n8k16 grid 4x8).  Double-buffered cp.async.
template <bool RELU, bool RES, bool QKV, bool OSPLIT, bool OF32>
__global__ void __launch_bounds__(256)
gemm_bf16(const uint16_t* __restrict__ Ahi, const uint16_t* __restrict__ Alo, int lda,
          const uint16_t* __restrict__ Bhi, const uint16_t* __restrict__ Blo, int ldb,
          const float* __restrict__ bias,
          const uint16_t* __restrict__ reshi, const uint16_t* __restrict__ reslo,
          float* __restrict__ C, uint16_t* __restrict__ Chi, uint16_t* __restrict__ Clo,
          int N, int K)
{
    extern __shared__ __align__(16) unsigned char dsm[];
    const int t = threadIdx.x;
    const int lane = t & 31, wid = t >> 5;
    const int wm = wid & 3, wn = wid >> 2;           // 4x2 warp grid
    const int n0 = blockIdx.x * BN;
    const int m0 = blockIdx.y * BM;
    const int acol0 = QKV ? (n0 % 768) : 0;          // QKV K-window
    const uint32_t sA0 = smem_u32(dsm);
    const uint32_t sB0 = sA0 + 2 * ASZ;

    float acc[4][8][4];
#pragma unroll
    for (int i = 0; i < 4; i++)
#pragma unroll
        for (int j = 0; j < 8; j++)
#pragma unroll
            for (int q = 0; q < 4; q++) acc[i][j][q] = 0.f;

    auto load_chunk = [&](int ck, int buf) {
        const int kb = acol0 + ck * BK;
#pragma unroll
        for (int i = 0; i < 8; i++) {                 // A: 2048 16B segs
            int seg = t + i * 256;
            int row = seg >> 3, part = seg & 7;
            int kk = (part & 3) * 8;
            const uint16_t* src = ((part < 4) ? Ahi : Alo) +
                                  (size_t)(m0 + row) * lda + kb + kk;
            uint32_t dst = sA0 + buf * ASZ +
                           (uint32_t)(row * KS + ((part < 4) ? 0 : 32) + kk) * 2;
            CP16(dst, src);
        }
        const int kb2 = ck * BK;
#pragma unroll
        for (int i = 0; i < 4; i++) {                 // B: 1024 16B segs
            int seg = t + i * 256;
            int row = seg >> 3, part = seg & 7;
            int kk = (part & 3) * 8;
            const uint16_t* src = ((part < 4) ? Bhi : Blo) +
                                  (size_t)(n0 + row) * ldb + kb2 + kk;
            uint32_t dst = sB0 + buf * BSZ +
                           (uint32_t)(row * KS + ((part < 4) ? 0 : 32) + kk) * 2;
            CP16(dst, src);
        }
    };

    const uint32_t aFr = sA0 + (uint32_t)((wm * 64 + (lane >> 2)) * KS + (lane & 3) * 2) * 2;
    const uint32_t bFr = sB0 + (uint32_t)((wn * 64 + (lane >> 2)) * KS + (lane & 3) * 2) * 2;
    // 6 k16 passes per 32-fp32 chunk: AhBh x2, AhBl x2, AlBh x2
    const int AO[6] = { 0, 16, 0, 16, 32, 48 };
    const int BO[6] = { 0, 16, 32, 48, 0, 16 };

    const int nck = K >> 5;
    load_chunk(0, 0); CP_COMMIT();

    for (int ck = 0; ck < nck; ck++) {
        const int buf = ck & 1;
        if (ck + 1 < nck) { load_chunk(ck + 1, buf ^ 1); CP_COMMIT(); CP_WAIT(1); }
        else              { CP_WAIT(0); }
        __syncthreads();
#pragma unroll
        for (int ps = 0; ps < 6; ps++) {
            const uint32_t aP = aFr + buf * ASZ + AO[ps] * 2;
            const uint32_t bP = bFr + buf * BSZ + BO[ps] * 2;
            uint32_t bf[8][2];
#pragma unroll
            for (int nt = 0; nt < 8; nt++) {
                bf[nt][0] = lds32(bP + nt * 8 * KS * 2);
                bf[nt][1] = lds32(bP + nt * 8 * KS * 2 + 16);
            }
#pragma unroll
            for (int mt = 0; mt < 4; mt++) {
                const uint32_t ab = aP + mt * 16 * KS * 2;
                uint32_t a0 = lds32(ab);
                uint32_t a1 = lds32(ab + 8 * KS * 2);
                uint32_t a2 = lds32(ab + 16);
                uint32_t a3 = lds32(ab + 8 * KS * 2 + 16);
#pragma unroll
                for (int nt = 0; nt < 8; nt++)
                    mma16816(acc[mt][nt][0], acc[mt][nt][1],
                             acc[mt][nt][2], acc[mt][nt][3],
                             a0, a1, a2, a3, bf[nt][0], bf[nt][1]);
            }
        }
        __syncthreads();
    }

    // epilogue
#pragma unroll
    for (int nt = 0; nt < 8; nt++) {
        const int c0 = n0 + wn * 64 + nt * 8 + (lane & 3) * 2;
        const float b0 = bias[c0], b1v = bias[c0 + 1];
#pragma unroll
        for (int mt = 0; mt < 4; mt++) {
            const int r0 = m0 + wm * 64 + mt * 16 + (lane >> 2);
#pragma unroll
            for (int half = 0; half < 2; half++) {
                const int r = r0 + half * 8;
                float v0 = acc[mt][nt][half * 2 + 0] + b0;
                float v1 = acc[mt][nt][half * 2 + 1] + b1v;
                if (RELU) { v0 = fmaxf(v0, 0.f); v1 = fmaxf(v1, 0.f); }
                const size_t off = (size_t)r * N + c0;
                if (RES) {
                    v0 += bf2f(reshi[off])     + bf2f(reslo[off]);
                    v1 += bf2f(reshi[off + 1]) + bf2f(reslo[off + 1]);
                }
                if (OF32) {
                    float2 o; o.x = v0; o.y = v1;
                    *(float2*)(C + off) = o;
                }
                if (OSPLIT) {
                    uint16_t h0, l0, h1, l1;
                    split1(v0, h0, l0); split1(v1, h1, l1);
                    *(uint32_t*)(Chi + off) = ((uint32_t)h1 << 16) | h0;
                    *(uint32_t*)(Clo + off) = ((uint32_t)l1 << 16) | l0;
                }
            }
        }
    }
}

// --------------------- weight / activation splitting -----------------------
__global__ void split_f32(const float* __restrict__ src, uint16_t* __restrict__ hi,
                          uint16_t* __restrict__ lo, int n)
{
    int i = blockIdx.x * 256 + threadIdx.x;
    if (i < n) { uint16_t h, l; split1(src[i], h, l); hi[i] = h; lo[i] = l; }
}

// packed block-diagonal QKV weight [NL][2304][128], split to hi/lo
__global__ void pack_qkv_w(const float* __restrict__ Wq, const float* __restrict__ Wk,
                           const float* __restrict__ Wv)
{
    int idx = blockIdx.x * 256 + threadIdx.x;
    if (idx >= NL * NQKV * 128) return;
    int l = idx / (NQKV * 128);
    int rem = idx % (NQKV * 128);
    int c = rem / 128, kk = rem % 128;
    int mat = c / 768, cw = c % 768;
    int h = cw / 64, e = cw % 64;
    int kwin = (cw / 128) * 128;
    int d = kwin + kk - h * 64;
    float val = 0.f;
    if (d >= 0 && d < 64) {
        const float* W = (mat == 0) ? Wq : (mat == 1 ? Wk : Wv);
        val = W[(((size_t)l * NH + h) * 64 + e) * 64 + d];
    }
    uint16_t hh, ll; split1(val, hh, ll);
    g_wqh[idx] = hh; g_wql[idx] = ll;
}
__global__ void pack_qkv_b(const float* __restrict__ bq, const float* __restrict__ bk,
                           const float* __restrict__ bv)
{
    int idx = blockIdx.x * 256 + threadIdx.x;
    if (idx >= NL * NQKV) return;
    int l = idx / NQKV, c = idx % NQKV;
    int mat = c / 768, cw = c % 768;
    int h = cw / 64, e = cw % 64;
    const float* b = (mat == 0) ? bq : (mat == 1 ? bk : bv);
    g_bp[idx] = b[((size_t)l * NH + h) * 64 + e];
}

// ---------------------------- patch embed ----------------------------------
__global__ void patch_embed_kernel(const float* __restrict__ batch,
                                   const float* __restrict__ Wp,
                                   const float* __restrict__ bp,
                                   const float* __restrict__ pos)
{
    __shared__ float px[36 * 36];
    __shared__ float Ws[128 * 36];
    const int bc = blockIdx.y, d0 = blockIdx.x * 128, t = threadIdx.x;
    const float* img = batch + bc * 1296;
    for (int e = t; e < 1296; e += 128) {
        int row = e / 36, col = e - row * 36;
        int s = (row / 6) * 6 + (col / 6);
        int p = (row % 6) * 6 + (col % 6);
        px[s * 36 + p] = img[e];
    }
    for (int i = t; i < 128 * 36; i += 128) Ws[i] = Wp[d0 * 36 + i];
    __syncthreads();
    const int d = d0 + t;
    float w[36];
#pragma unroll
    for (int p = 0; p < 36; p++) w[p] = Ws[t * 36 + p];
    const float bias = bp[d];
    for (int s = 0; s < 36; s++) {
        float acc = bias + pos[s * 768 + d];
        const float* pr = &px[s * 36];
#pragma unroll
        for (int p = 0; p < 36; p++) acc = fmaf(pr[p], w[p], acc);
        g_z[(size_t)(bc * 36 + s) * 768 + d] = acc;
    }
}

// ------------------------ LayerNorm -> hi/lo bf16 --------------------------
__global__ void ln_split(const float* __restrict__ in, uint16_t* __restrict__ hi,
                         uint16_t* __restrict__ lo, const float* __restrict__ gamma,
                         const float* __restrict__ beta)
{
    const int row = blockIdx.x;
    const float* x = in + (size_t)row * 768;
    const int t = threadIdx.x;
    float v0 = x[t], v1 = x[t + 256], v2 = x[t + 512];
    float s = v0 + v1 + v2;
    float q = v0 * v0 + v1 * v1 + v2 * v2;
#pragma unroll
    for (int o = 16; o > 0; o >>= 1) {
        s += __shfl_xor_sync(0xffffffffu, s, o);
        q += __shfl_xor_sync(0xffffffffu, q, o);
    }
    __shared__ float rs[8], rq[8];
    __shared__ float smean, srstd;
    if ((t & 31) == 0) { rs[t >> 5] = s; rq[t >> 5] = q; }
    __syncthreads();
    if (t == 0) {
        float S = 0.f, Q = 0.f;
#pragma unroll
        for (int i = 0; i < 8; i++) { S += rs[i]; Q += rq[i]; }
        float m = S * (1.0f / 768.0f);
        float var = Q * (1.0f / 768.0f) - m * m;
        smean = m; srstd = rsqrtf(var + 1e-5f);
    }
    __syncthreads();
    const float m = smean, r = srstd;
    const size_t base = (size_t)row * 768;
    float y0 = (v0 - m) * r * gamma[t]       + beta[t];
    float y1 = (v1 - m) * r * gamma[t + 256] + beta[t + 256];
    float y2 = (v2 - m) * r * gamma[t + 512] + beta[t + 512];
    uint16_t h, l;
    split1(y0, h, l); hi[base + t]       = h; lo[base + t]       = l;
    split1(y1, h, l); hi[base + t + 256] = h; lo[base + t + 256] = l;
    split1(y2, h, l); hi[base + t + 512] = h; lo[base + t + 512] = l;
}

// ---------------------------- attention ------------------------------------
#define QK_STRIDE 67
#define V_STRIDE  66
__global__ void __launch_bounds__(256) attn_kernel()
{
    __shared__ float Qs[36 * QK_STRIDE], Ks[36 * QK_STRIDE];
    __shared__ float Vs[36 * V_STRIDE];
    __shared__ float P[36 * 40];
    const int bc = blockIdx.x, h = blockIdx.y, t = threadIdx.x;
    const size_t qbase = (size_t)bc * 36 * NQKV + h * 64;

    for (int idx = t; idx < 2304; idx += 256) {
        int s = idx >> 6, e = idx & 63;
        size_t g = qbase + (size_t)s * NQKV + e;
        Qs[s * QK_STRIDE + e] = g_qkv[g];
        Ks[s * QK_STRIDE + e] = g_qkv[g + 768];
        Vs[s * V_STRIDE  + e] = g_qkv[g + 1536];
    }
    __syncthreads();

    for (int vt = t; vt < 324; vt += 256) {      // 18x18 of 2x2 score tiles
        int i0 = (vt / 18) * 2, j0 = (vt % 18) * 2;
        const float* q0 = &Qs[i0 * QK_STRIDE]; const float* q1 = q0 + QK_STRIDE;
        const float* k0 = &Ks[j0 * QK_STRIDE]; const float* k1 = k0 + QK_STRIDE;
        float a00 = 0.f, a01 = 0.f, a10 = 0.f, a11 = 0.f;
#pragma unroll
        for (int e = 0; e < 64; e++) {
            float qa = q0[e], qb = q1[e], ka = k0[e], kb = k1[e];
            a00 = fmaf(qa, ka, a00); a01 = fmaf(qa, kb, a01);
            a10 = fmaf(qb, ka, a10); a11 = fmaf(qb, kb, a11);
        }
        P[i0 * 40 + j0]           = a00 * 0.125f;
        P[i0 * 40 + j0 + 1]       = a01 * 0.125f;
        P[(i0 + 1) * 40 + j0]     = a10 * 0.125f;
        P[(i0 + 1) * 40 + j0 + 1] = a11 * 0.125f;
    }
    __syncthreads();

    if (t < 36) {
        float mx = -1e30f;
        for (int j = 0; j < 36; j++) mx = fmaxf(mx, P[t * 40 + j]);
        float sum = 0.f;
        for (int j = 0; j < 36; j++) {
            float ex = expf(P[t * 40 + j] - mx);
            P[t * 40 + j] = ex;
            sum += ex;
        }
        float inv = 1.f / sum;
        for (int j = 0; j < 36; j++) P[t * 40 + j] *= inv;
    }
    __syncthreads();

    float* zr = g_z + (size_t)bc * 36 * 768 + h * 64;
    for (int vt = t; vt < 576; vt += 256) {      // 18 rows x 32 col pairs
        int i0 = (vt / 32) * 2, e0 = (vt % 32) * 2;
        const float* p0 = &P[i0 * 40]; const float* p1 = p0 + 40;
        float a00 = 0.f, a01 = 0.f, a10 = 0.f, a11 = 0.f;
#pragma unroll
        for (int j = 0; j < 36; j++) {
            float2 v = *(const float2*)&Vs[j * V_STRIDE + e0];
            float w0 = p0[j], w1 = p1[j];
            a00 = fmaf(w0, v.x, a00); a01 = fmaf(w0, v.y, a01);
            a10 = fmaf(w1, v.x, a10); a11 = fmaf(w1, v.y, a11);
        }
        float* z0 = zr + (size_t)i0 * 768 + e0;
        z0[0]   += a00; z0[1]   += a01;
        z0[768] += a10; z0[769] += a11;
    }
}

// ------------------------------- launch ------------------------------------
extern "C" void kernel_launch(void* const* d_in, const int* in_sizes, int n_in,
                              void* d_out, int out_size)
{
    (void)in_sizes; (void)n_in; (void)out_size;
    const float* batch = (const float*)d_in[0];
    const float* Wp    = (const float*)d_in[1];
    const float* bp    = (const float*)d_in[2];
    const float* pos   = (const float*)d_in[3];
    const float* ln1g  = (const float*)d_in[4];
    const float* ln1b  = (const float*)d_in[5];
    const float* Wq    = (const float*)d_in[6];
    const float* bq    = (const float*)d_in[7];
    const float* Wk    = (const float*)d_in[8];
    const float* bk    = (const float*)d_in[9];
    const float* Wv    = (const float*)d_in[10];
    const float* bv    = (const float*)d_in[11];
    const float* ln2g  = (const float*)d_in[12];
    const float* ln2b  = (const float*)d_in[13];
    const float* W1    = (const float*)d_in[14];
    const float* b1    = (const float*)d_in[15];
    const float* W2    = (const float*)d_in[16];
    const float* b2    = (const float*)d_in[17];
    const float* Wout  = (const float*)d_in[18];
    const float* bout  = (const float*)d_in[19];

    float *zp, *qkvp, *bpp;
    uint16_t *hh, *hl, *mh, *ml, *w1h, *w1l, *w2h, *w2l, *wqh, *wql, *woh, *wol;
    cudaGetSymbolAddress((void**)&zp,   g_z);
    cudaGetSymbolAddress((void**)&qkvp, g_qkv);
    cudaGetSymbolAddress((void**)&bpp,  g_bp);
    cudaGetSymbolAddress((void**)&hh,   g_hh);
    cudaGetSymbolAddress((void**)&hl,   g_hl);
    cudaGetSymbolAddress((void**)&mh,   g_mh);
    cudaGetSymbolAddress((void**)&ml,   g_ml);
    cudaGetSymbolAddress((void**)&w1h,  g_w1h);
    cudaGetSymbolAddress((void**)&w1l,  g_w1l);
    cudaGetSymbolAddress((void**)&w2h,  g_w2h);
    cudaGetSymbolAddress((void**)&w2l,  g_w2l);
    cudaGetSymbolAddress((void**)&wqh,  g_wqh);
    cudaGetSymbolAddress((void**)&wql,  g_wql);
    cudaGetSymbolAddress((void**)&woh,  g_woh);
    cudaGetSymbolAddress((void**)&wol,  g_wol);

    // opt-in smem for all GEMM instantiations
    cudaFuncSetAttribute(gemm_bf16<false,false,true ,false,true >,
                         cudaFuncAttributeMaxDynamicSharedMemorySize, SMEM_BYTES);
    cudaFuncSetAttribute(gemm_bf16<true ,false,false,true ,false>,
                         cudaFuncAttributeMaxDynamicSharedMemorySize, SMEM_BYTES);
    cudaFuncSetAttribute(gemm_bf16<false,true ,false,false,true >,
                         cudaFuncAttributeMaxDynamicSharedMemorySize, SMEM_BYTES);
    cudaFuncSetAttribute(gemm_bf16<false,false,false,false,true >,
                         cudaFuncAttributeMaxDynamicSharedMemorySize, SMEM_BYTES);

    // weight splits (per launch; cheap)
    const int nW1 = NL * DMLP * DD;
    split_f32<<<(nW1 + 255) / 256, 256>>>(W1, w1h, w1l, nW1);
    split_f32<<<(nW1 + 255) / 256, 256>>>(W2, w2h, w2l, nW1);
    split_f32<<<(DOUT * DD + 255) / 256, 256>>>(Wout, woh, wol, DOUT * DD);
    pack_qkv_w<<<(NL * NQKV * 128 + 255) / 256, 256>>>(Wq, Wk, Wv);
    pack_qkv_b<<<(NL * NQKV + 255) / 256, 256>>>(bq, bk, bv);

    patch_embed_kernel<<<dim3(6, NBC), 128>>>(batch, Wp, bp, pos);

    const dim3 gQ(NQKV / BN, NT / BM);
    const dim3 g1(DMLP / BN, NT / BM);
    const dim3 g2(DD / BN, NT / BM);
    const dim3 gO(DOUT / BN, NT / BM);

    for (int l = 0; l < NL; l++) {
        ln_split<<<NT, 256>>>(zp, hh, hl, ln1g + l * 768, ln1b + l * 768);
        gemm_bf16<false,false,true,false,true><<<gQ, 256, SMEM_BYTES>>>(
            hh, hl, 768, wqh + (size_t)l * NQKV * 128, wql + (size_t)l * NQKV * 128, 128,
            bpp + l * NQKV, nullptr, nullptr, qkvp, nullptr, nullptr, NQKV, 128);
        attn_kernel<<<dim3(NBC, NH), 256>>>();
        ln_split<<<NT, 256>>>(zp, hh, hl, ln2g + l * 768, ln2b + l * 768);
        gemm_bf16<true,false,false,true,false><<<g1, 256, SMEM_BYTES>>>(
            hh, hl, 768, w1h + (size_t)l * DMLP * DD, w1l + (size_t)l * DMLP * DD, 768,
            b1 + l * DMLP, nullptr, nullptr, nullptr, mh, ml, DMLP, 768);
        gemm_bf16<false,true,false,false,true><<<g2, 256, SMEM_BYTES>>>(
            mh, ml, 1536, w2h + (size_t)l * DD * DMLP, w2l + (size_t)l * DD * DMLP, 1536,
            b2 + l * 768, hh, hl, zp, nullptr, nullptr, DD, 1536);
    }

    // final z -> hi/lo, then out projection
    split_f32<<<(NT * DD + 255) / 256, 256>>>(zp, hh, hl, NT * DD);
    gemm_bf16<false,false,false,false,true><<<gO, 256, SMEM_BYTES>>>(
        hh, hl, 768, woh, wol, 768, bout, nullptr, nullptr,
        (float*)d_out, nullptr, nullptr, DOUT, 768);
}

// round 14
// speedup vs baseline: 2.0585x; 1.0727x over previous
#include <cuda_runtime.h>
#include <cuda_bf16.h>
#include <cstdint>

// ---------------------------------------------------------------------------
// FeatureExtractorViT (B=512,C=3,IMG=36,PS=6,S=36,D=768,H=12,HD=64,L=4,OUT=256)
// NT = 55296 tokens.  GEMMs via mma.sync bf16 (HMMA) with split-bf16 3-pass
// accumulation (fp32-grade).  Mainloop uses ldmatrix.x4 fragment loads.
// ---------------------------------------------------------------------------

#define NT    55296
#define DD    768
#define NBC   1536
#define NH    12
#define NL    4
#define DOUT  256
#define DMLP  1536
#define NQKV  2304

// GEMM tiling
#define BM 256
#define BN 128
#define BK 32              // fp32 k per chunk (bf16 cols: hi 0..31, lo 32..63)
#define KS 72              // smem row stride in bf16 (144 B, conflict-free)
#define ASZ (BM * KS * 2)  // bytes per A buffer
#define BSZ (BN * KS * 2)
#define SMEM_BYTES (2 * ASZ + 2 * BSZ)   // 110592

// ---------------- scratch (device globals; no runtime alloc) ---------------
static __device__ float    g_z[(size_t)NT * DD];       // residual stream (fp32)
static __device__ float    g_qkv[(size_t)NT * NQKV];   // q|k|v (fp32)
static __device__ uint16_t g_hh[(size_t)NT * DD];      // LN out hi (bf16 bits)
static __device__ uint16_t g_hl[(size_t)NT * DD];      // LN out lo
static __device__ uint16_t g_mh[(size_t)NT * DMLP];    // MLP hidden hi
static __device__ uint16_t g_ml[(size_t)NT * DMLP];    // MLP hidden lo
static __device__ uint16_t g_w1h[(size_t)NL * DMLP * DD], g_w1l[(size_t)NL * DMLP * DD];
static __device__ uint16_t g_w2h[(size_t)NL * DD * DMLP], g_w2l[(size_t)NL * DD * DMLP];
static __device__ uint16_t g_wqh[(size_t)NL * NQKV * 128], g_wql[(size_t)NL * NQKV * 128];
static __device__ uint16_t g_woh[(size_t)DOUT * DD], g_wol[(size_t)DOUT * DD];
static __device__ float    g_bp[(size_t)NL * NQKV];

// ---------------------------- helpers --------------------------------------
__device__ __forceinline__ uint32_t smem_u32(const void* p) {
    uint32_t a;
    asm("{ .reg .u64 t; cvta.to.shared.u64 t, %1; cvt.u32.u64 %0, t; }"
        : "=r"(a) : "l"(p));
    return a;
}
__device__ __forceinline__ float bf2f(uint16_t b) {
    return __uint_as_float((uint32_t)b << 16);
}
__device__ __forceinline__ void split1(float x, uint16_t& h, uint16_t& l) {
    __nv_bfloat16 hb = __float2bfloat16_rn(x);
    h = __bfloat16_as_ushort(hb);
    l = __bfloat16_as_ushort(__float2bfloat16_rn(x - __bfloat162float(hb)));
}
__device__ __forceinline__ void mma16816(float& d0, float& d1, float& d2, float& d3,
                                         uint32_t a0, uint32_t a1, uint32_t a2,
                                         uint32_t a3, uint32_t b0, uint32_t b1) {
    asm("mma.sync.aligned.m16n8k16.row.col.f32.bf16.bf16.f32 "
        "{%0,%1,%2,%3}, {%4,%5,%6,%7}, {%8,%9}, {%0,%1,%2,%3};"
        : "+f"(d0), "+f"(d1), "+f"(d2), "+f"(d3)
        : "r"(a0), "r"(a1), "r"(a2), "r"(a3), "r"(b0), "r"(b1));
}
__device__ __forceinline__ void ldsm4(uint32_t& r0, uint32_t& r1, uint32_t& r2,
                                      uint32_t& r3, uint32_t addr) {
    asm volatile("ldmatrix.sync.aligned.m8n8.x4.shared.b16 {%0,%1,%2,%3}, [%4];"
                 : "=r"(r0), "=r"(r1), "=r"(r2), "=r"(r3) : "r"(addr));
}
#define CP16(dst, src) \
    asm volatile("cp.async.ca.shared.global [%0], [%1], 16;" :: "r"(dst), "l"(src))
#define CP_COMMIT() asm volatile("cp.async.commit_group;" ::: "memory")
#define CP_WAIT(n)  asm volatile("cp.async.wait_group %0;" :: "n"(n) : "memory")

// ---------------------- GEMM: C = A @ B^T (+bias,+relu,+res) ---------------
// A: [M,K] hi/lo bf16 (lda);  B: [N,K] hi/lo bf16 (ldb).
// C = Ah*Bh + Ah*Bl + Al*Bh (fp32 acc).  Tile 256x128, 8 warps (4x2),
// warp tile 64x64.  Double-buffered cp.async; ldmatrix fragment loads.
template <bool RELU, bool RES, bool QKV, bool OSPLIT, bool OF32>
__global__ void __launch_bounds__(256)
gemm_bf16(const uint16_t* __restrict__ Ahi, const uint16_t* __restrict__ Alo, int lda,
          const uint16_t* __restrict__ Bhi, const uint16_t* __restrict__ Blo, int ldb,
          const float* __restrict__ bias,
          const uint16_t* __restrict__ reshi, const uint16_t* __restrict__ reslo,
          float* __restrict__ C, uint16_t* __restrict__ Chi, uint16_t* __restrict__ Clo,
          int N, int K)
{
    extern __shared__ __align__(16) unsigned char dsm[];
    const int t = threadIdx.x;
    const int lane = t & 31, wid = t >> 5;
    const int wm = wid & 3, wn = wid >> 2;           // 4x2 warp grid
    const int n0 = blockIdx.x * BN;
    const int m0 = blockIdx.y * BM;
    const int acol0 = QKV ? (n0 % 768) : 0;          // QKV K-window
    const uint32_t sA0 = smem_u32(dsm);
    const uint32_t sB0 = sA0 + 2 * ASZ;

    float acc[4][8][4];
#pragma unroll
    for (int i = 0; i < 4; i++)
#pragma unroll
        for (int j = 0; j < 8; j++)
#pragma unroll
            for (int q = 0; q < 4; q++) acc[i][j][q] = 0.f;

    auto load_chunk = [&](int ck, int buf) {
        const int kb = acol0 + ck * BK;
#pragma unroll
        for (int i = 0; i < 8; i++) {                 // A: 2048 16B segs
            int seg = t + i * 256;
            int row = seg >> 3, part = seg & 7;
            int kk = (part & 3) * 8;
            const uint16_t* src = ((part < 4) ? Ahi : Alo) +
                                  (size_t)(m0 + row) * lda + kb + kk;
            uint32_t dst = sA0 + buf * ASZ +
                           (uint32_t)(row * KS + ((part < 4) ? 0 : 32) + kk) * 2;
            CP16(dst, src);
        }
        const int kb2 = ck * BK;
#pragma unroll
        for (int i = 0; i < 4; i++) {                 // B: 1024 16B segs
            int seg = t + i * 256;
            int row = seg >> 3, part = seg & 7;
            int kk = (part & 3) * 8;
            const uint16_t* src = ((part < 4) ? Bhi : Blo) +
                                  (size_t)(n0 + row) * ldb + kb2 + kk;
            uint32_t dst = sB0 + buf * BSZ +
                           (uint32_t)(row * KS + ((part < 4) ? 0 : 32) + kk) * 2;
            CP16(dst, src);
        }
    };

    // ldmatrix per-lane addresses.
    // A x4: matrices a0(r0-7,k0) a1(r8-15,k0) a2(r0-7,k8) a3(r8-15,k8)
    const int aRow = (lane & 7) + ((lane >> 3) & 1) * 8;
    const int aCol = (lane >> 4) * 8;
    const uint32_t aAddr = sA0 + (uint32_t)((wm * 64 + aRow) * KS + aCol) * 2;
    // B x4: b0(n0-7,k0) b1(n0-7,k8) b2(n8-15,k0) b3(n8-15,k8)
    const int bRow = (lane & 7) + (lane >> 4) * 8;
    const int bCol = ((lane >> 3) & 1) * 8;
    const uint32_t bAddr = sB0 + (uint32_t)((wn * 64 + bRow) * KS + bCol) * 2;

    const int nck = K >> 5;
    load_chunk(0, 0); CP_COMMIT();

    for (int ck = 0; ck < nck; ck++) {
        const int buf = ck & 1;
        if (ck + 1 < nck) { load_chunk(ck + 1, buf ^ 1); CP_COMMIT(); CP_WAIT(1); }
        else              { CP_WAIT(0); }
        __syncthreads();
        const uint32_t aB = aAddr + buf * ASZ;
        const uint32_t bB = bAddr + buf * BSZ;
#pragma unroll
        for (int ko = 0; ko < 32; ko += 16) {
            uint32_t ah[4][4], al[4][4], bb[4][4];
#pragma unroll
            for (int mt = 0; mt < 4; mt++)
                ldsm4(ah[mt][0], ah[mt][1], ah[mt][2], ah[mt][3],
                      aB + (uint32_t)(mt * 16 * KS + ko) * 2);
#pragma unroll
            for (int mt = 0; mt < 4; mt++)
                ldsm4(al[mt][0], al[mt][1], al[mt][2], al[mt][3],
                      aB + (uint32_t)(mt * 16 * KS + ko + 32) * 2);
#pragma unroll
            for (int p = 0; p < 4; p++)        // B hi (2 n-tiles per x4)
                ldsm4(bb[p][0], bb[p][1], bb[p][2], bb[p][3],
                      bB + (uint32_t)(p * 16 * KS + ko) * 2);
            // Ah * Bh
#pragma unroll
            for (int mt = 0; mt < 4; mt++)
#pragma unroll
                for (int p = 0; p < 4; p++) {
                    mma16816(acc[mt][2*p][0], acc[mt][2*p][1], acc[mt][2*p][2], acc[mt][2*p][3],
                             ah[mt][0], ah[mt][1], ah[mt][2], ah[mt][3], bb[p][0], bb[p][1]);
                    mma16816(acc[mt][2*p+1][0], acc[mt][2*p+1][1], acc[mt][2*p+1][2], acc[mt][2*p+1][3],
                             ah[mt][0], ah[mt][1], ah[mt][2], ah[mt][3], bb[p][2], bb[p][3]);
                }
            // Al * Bh  (B hi frags reused)
#pragma unroll
            for (int mt = 0; mt < 4; mt++)
#pragma unroll
                for (int p = 0; p < 4; p++) {
                    mma16816(acc[mt][2*p][0], acc[mt][2*p][1], acc[mt][2*p][2], acc[mt][2*p][3],
                             al[mt][0], al[mt][1], al[mt][2], al[mt][3], bb[p][0], bb[p][1]);
                    mma16816(acc[mt][2*p+1][0], acc[mt][2*p+1][1], acc[mt][2*p+1][2], acc[mt][2*p+1][3],
                             al[mt][0], al[mt][1], al[mt][2], al[mt][3], bb[p][2], bb[p][3]);
                }
            // B lo (overwrite), then Ah * Bl
#pragma unroll
            for (int p = 0; p < 4; p++)
                ldsm4(bb[p][0], bb[p][1], bb[p][2], bb[p][3],
                      bB + (uint32_t)(p * 16 * KS + ko + 32) * 2);
#pragma unroll
            for (int mt = 0; mt < 4; mt++)
#pragma unroll
                for (int p = 0; p < 4; p++) {
                    mma16816(acc[mt][2*p][0], acc[mt][2*p][1], acc[mt][2*p][2], acc[mt][2*p][3],
                             ah[mt][0], ah[mt][1], ah[mt][2], ah[mt][3], bb[p][0], bb[p][1]);
                    mma16816(acc[mt][2*p+1][0], acc[mt][2*p+1][1], acc[mt][2*p+1][2], acc[mt][2*p+1][3],
                             ah[mt][0], ah[mt][1], ah[mt][2], ah[mt][3], bb[p][2], bb[p][3]);
                }
        }
        __syncthreads();
    }

    // epilogue
#pragma unroll
    for (int nt = 0; nt < 8; nt++) {
        const int c0 = n0 + wn * 64 + nt * 8 + (lane & 3) * 2;
        const float b0 = bias[c0], b1v = bias[c0 + 1];
#pragma unroll
        for (int mt = 0; mt < 4; mt++) {
            const int r0 = m0 + wm * 64 + mt * 16 + (lane >> 2);
#pragma unroll
            for (int half = 0; half < 2; half++) {
                const int r = r0 + half * 8;
                float v0 = acc[mt][nt][half * 2 + 0] + b0;
                float v1 = acc[mt][nt][half * 2 + 1] + b1v;
                if (RELU) { v0 = fmaxf(v0, 0.f); v1 = fmaxf(v1, 0.f); }
                const size_t off = (size_t)r * N + c0;
                if (RES) {
                    v0 += bf2f(reshi[off])     + bf2f(reslo[off]);
                    v1 += bf2f(reshi[off + 1]) + bf2f(reslo[off + 1]);
                }
                if (OF32) {
                    float2 o; o.x = v0; o.y = v1;
                    *(float2*)(C + off) = o;
                }
                if (OSPLIT) {
                    uint16_t h0, l0, h1, l1;
                    split1(v0, h0, l0); split1(v1, h1, l1);
                    *(uint32_t*)(Chi + off) = ((uint32_t)h1 << 16) | h0;
                    *(uint32_t*)(Clo + off) = ((uint32_t)l1 << 16) | l0;
                }
            }
        }
    }
}

// --------------------- weight / activation splitting -----------------------
__global__ void split_f32(const float* __restrict__ src, uint16_t* __restrict__ hi,
                          uint16_t* __restrict__ lo, int n)
{
    int i = blockIdx.x * 256 + threadIdx.x;
    if (i < n) { uint16_t h, l; split1(src[i], h, l); hi[i] = h; lo[i] = l; }
}

__global__ void pack_qkv_w(const float* __restrict__ Wq, const float* __restrict__ Wk,
                           const float* __restrict__ Wv)
{
    int idx = blockIdx.x * 256 + threadIdx.x;
    if (idx >= NL * NQKV * 128) return;
    int l = idx / (NQKV * 128);
    int rem = idx % (NQKV * 128);
    int c = rem / 128, kk = rem % 128;
    int mat = c / 768, cw = c % 768;
    int h = cw / 64, e = cw % 64;
    int kwin = (cw / 128) * 128;
    int d = kwin + kk - h * 64;
    float val = 0.f;
    if (d >= 0 && d < 64) {
        const float* W = (mat == 0) ? Wq : (mat == 1 ? Wk : Wv);
        val = W[(((size_t)l * NH + h) * 64 + e) * 64 + d];
    }
    uint16_t hh, ll; split1(val, hh, ll);
    g_wqh[idx] = hh; g_wql[idx] = ll;
}
__global__ void pack_qkv_b(const float* __restrict__ bq, const float* __restrict__ bk,
                           const float* __restrict__ bv)
{
    int idx = blockIdx.x * 256 + threadIdx.x;
    if (idx >= NL * NQKV) return;
    int l = idx / NQKV, c = idx % NQKV;
    int mat = c / 768, cw = c % 768;
    int h = cw / 64, e = cw % 64;
    const float* b = (mat == 0) ? bq : (mat == 1 ? bk : bv);
    g_bp[idx] = b[((size_t)l * NH + h) * 64 + e];
}

// ---------------------------- patch embed ----------------------------------
__global__ void patch_embed_kernel(const float* __restrict__ batch,
                                   const float* __restrict__ Wp,
                                   const float* __restrict__ bp,
                                   const float* __restrict__ pos)
{
    __shared__ float px[36 * 36];
    __shared__ float Ws[128 * 36];
    const int bc = blockIdx.y, d0 = blockIdx.x * 128, t = threadIdx.x;
    const float* img = batch + bc * 1296;
    for (int e = t; e < 1296; e += 128) {
        int row = e / 36, col = e - row * 36;
        int s = (row / 6) * 6 + (col / 6);
        int p = (row % 6) * 6 + (col % 6);
        px[s * 36 + p] = img[e];
    }
    for (int i = t; i < 128 * 36; i += 128) Ws[i] = Wp[d0 * 36 + i];
    __syncthreads();
    const int d = d0 + t;
    float w[36];
#pragma unroll
    for (int p = 0; p < 36; p++) w[p] = Ws[t * 36 + p];
    const float bias = bp[d];
    for (int s = 0; s < 36; s++) {
        float acc = bias + pos[s * 768 + d];
        const float* pr = &px[s * 36];
#pragma unroll
        for (int p = 0; p < 36; p++) acc = fmaf(pr[p], w[p], acc);
        g_z[(size_t)(bc * 36 + s) * 768 + d] = acc;
    }
}

// ------------------------ LayerNorm -> hi/lo bf16 --------------------------
__global__ void ln_split(const float* __restrict__ in, uint16_t* __restrict__ hi,
                         uint16_t* __restrict__ lo, const float* __restrict__ gamma,
                         const float* __restrict__ beta)
{
    const int row = blockIdx.x;
    const float* x = in + (size_t)row * 768;
    const int t = threadIdx.x;
    float v0 = x[t], v1 = x[t + 256], v2 = x[t + 512];
    float s = v0 + v1 + v2;
    float q = v0 * v0 + v1 * v1 + v2 * v2;
#pragma unroll
    for (int o = 16; o > 0; o >>= 1) {
        s += __shfl_xor_sync(0xffffffffu, s, o);
        q += __shfl_xor_sync(0xffffffffu, q, o);
    }
    __shared__ float rs[8], rq[8];
    __shared__ float smean, srstd;
    if ((t & 31) == 0) { rs[t >> 5] = s; rq[t >> 5] = q; }
    __syncthreads();
    if (t == 0) {
        float S = 0.f, Q = 0.f;
#pragma unroll
        for (int i = 0; i < 8; i++) { S += rs[i]; Q += rq[i]; }
        float m = S * (1.0f / 768.0f);
        float var = Q * (1.0f / 768.0f) - m * m;
        smean = m; srstd = rsqrtf(var + 1e-5f);
    }
    __syncthreads();
    const float m = smean, r = srstd;
    const size_t base = (size_t)row * 768;
    float y0 = (v0 - m) * r * gamma[t]       + beta[t];
    float y1 = (v1 - m) * r * gamma[t + 256] + beta[t + 256];
    float y2 = (v2 - m) * r * gamma[t + 512] + beta[t + 512];
    uint16_t h, l;
    split1(y0, h, l); hi[base + t]       = h; lo[base + t]       = l;
    split1(y1, h, l); hi[base + t + 256] = h; lo[base + t + 256] = l;
    split1(y2, h, l); hi[base + t + 512] = h; lo[base + t + 512] = l;
}

// ---------------------------- attention ------------------------------------
#define QK_STRIDE 67
#define V_STRIDE  66
__global__ void __launch_bounds__(256) attn_kernel()
{
    __shared__ float Qs[36 * QK_STRIDE], Ks[36 * QK_STRIDE];
    __shared__ float Vs[36 * V_STRIDE];
    __shared__ float P[36 * 40];
    const int bc = blockIdx.x, h = blockIdx.y, t = threadIdx.x;
    const size_t qbase = (size_t)bc * 36 * NQKV + h * 64;

    for (int idx = t; idx < 2304; idx += 256) {
        int s = idx >> 6, e = idx & 63;
        size_t g = qbase + (size_t)s * NQKV + e;
        Qs[s * QK_STRIDE + e] = g_qkv[g] * 0.125f;   // fold 1/sqrt(64)
        Ks[s * QK_STRIDE + e] = g_qkv[g + 768];
        Vs[s * V_STRIDE  + e] = g_qkv[g + 1536];
    }
    __syncthreads();

    for (int vt = t; vt < 324; vt += 256) {      // 18x18 of 2x2 score tiles
        int i0 = (vt / 18) * 2, j0 = (vt % 18) * 2;
        const float* q0 = &Qs[i0 * QK_STRIDE]; const float* q1 = q0 + QK_STRIDE;
        const float* k0 = &Ks[j0 * QK_STRIDE]; const float* k1 = k0 + QK_STRIDE;
        float a00 = 0.f, a01 = 0.f, a10 = 0.f, a11 = 0.f;
#pragma unroll
        for (int e = 0; e < 64; e++) {
            float qa = q0[e], qb = q1[e], ka = k0[e], kb = k1[e];
            a00 = fmaf(qa, ka, a00); a01 = fmaf(qa, kb, a01);
            a10 = fmaf(qb, ka, a10); a11 = fmaf(qb, kb, a11);
        }
        P[i0 * 40 + j0]           = a00;
        P[i0 * 40 + j0 + 1]       = a01;
        P[(i0 + 1) * 40 + j0]     = a10;
        P[(i0 + 1) * 40 + j0 + 1] = a11;
    }
    __syncthreads();

    if (t < 36) {
        float mx = -1e30f;
        for (int j = 0; j < 36; j++) mx = fmaxf(mx, P[t * 40 + j]);
        float sum = 0.f;
        for (int j = 0; j < 36; j++) {
            float ex = expf(P[t * 40 + j] - mx);
            P[t * 40 + j] = ex;
            sum += ex;
        }
        float inv = 1.f / sum;
        for (int j = 0; j < 36; j++) P[t * 40 + j] *= inv;
    }
    __syncthreads();

    float* zr = g_z + (size_t)bc * 36 * 768 + h * 64;
    for (int vt = t; vt < 576; vt += 256) {      // 18 rows x 32 col pairs
        int i0 = (vt / 32) * 2, e0 = (vt % 32) * 2;
        const float* p0 = &P[i0 * 40]; const float* p1 = p0 + 40;
        float a00 = 0.f, a01 = 0.f, a10 = 0.f, a11 = 0.f;
#pragma unroll
        for (int j = 0; j < 36; j++) {
            float2 v = *(const float2*)&Vs[j * V_STRIDE + e0];
            float w0 = p0[j], w1 = p1[j];
            a00 = fmaf(w0, v.x, a00); a01 = fmaf(w0, v.y, a01);
            a10 = fmaf(w1, v.x, a10); a11 = fmaf(w1, v.y, a11);
        }
        float* z0 = zr + (size_t)i0 * 768 + e0;
        z0[0]   += a00; z0[1]   += a01;
        z0[768] += a10; z0[769] += a11;
    }
}

// ------------------------------- launch ------------------------------------
extern "C" void kernel_launch(void* const* d_in, const int* in_sizes, int n_in,
                              void* d_out, int out_size)
{
    (void)in_sizes; (void)n_in; (void)out_size;
    const float* batch = (const float*)d_in[0];
    const float* Wp    = (const float*)d_in[1];
    const float* bp    = (const float*)d_in[2];
    const float* pos   = (const float*)d_in[3];
    const float* ln1g  = (const float*)d_in[4];
    const float* ln1b  = (const float*)d_in[5];
    const float* Wq    = (const float*)d_in[6];
    const float* bq    = (const float*)d_in[7];
    const float* Wk    = (const float*)d_in[8];
    const float* bk    = (const float*)d_in[9];
    const float* Wv    = (const float*)d_in[10];
    const float* bv    = (const float*)d_in[11];
    const float* ln2g  = (const float*)d_in[12];
    const float* ln2b  = (const float*)d_in[13];
    const float* W1    = (const float*)d_in[14];
    const float* b1    = (const float*)d_in[15];
    const float* W2    = (const float*)d_in[16];
    const float* b2    = (const float*)d_in[17];
    const float* Wout  = (const float*)d_in[18];
    const float* bout  = (const float*)d_in[19];

    float *zp, *qkvp, *bpp;
    uint16_t *hh, *hl, *mh, *ml, *w1h, *w1l, *w2h, *w2l, *wqh, *wql, *woh, *wol;
    cudaGetSymbolAddress((void**)&zp,   g_z);
    cudaGetSymbolAddress((void**)&qkvp, g_qkv);
    cudaGetSymbolAddress((void**)&bpp,  g_bp);
    cudaGetSymbolAddress((void**)&hh,   g_hh);
    cudaGetSymbolAddress((void**)&hl,   g_hl);
    cudaGetSymbolAddress((void**)&mh,   g_mh);
    cudaGetSymbolAddress((void**)&ml,   g_ml);
    cudaGetSymbolAddress((void**)&w1h,  g_w1h);
    cudaGetSymbolAddress((void**)&w1l,  g_w1l);
    cudaGetSymbolAddress((void**)&w2h,  g_w2h);
    cudaGetSymbolAddress((void**)&w2l,  g_w2l);
    cudaGetSymbolAddress((void**)&wqh,  g_wqh);
    cudaGetSymbolAddress((void**)&wql,  g_wql);
    cudaGetSymbolAddress((void**)&woh,  g_woh);
    cudaGetSymbolAddress((void**)&wol,  g_wol);

    cudaFuncSetAttribute(gemm_bf16<false,false,true ,false,true >,
                         cudaFuncAttributeMaxDynamicSharedMemorySize, SMEM_BYTES);
    cudaFuncSetAttribute(gemm_bf16<true ,false,false,true ,false>,
                         cudaFuncAttributeMaxDynamicSharedMemorySize, SMEM_BYTES);
    cudaFuncSetAttribute(gemm_bf16<false,true ,false,false,true >,
                         cudaFuncAttributeMaxDynamicSharedMemorySize, SMEM_BYTES);
    cudaFuncSetAttribute(gemm_bf16<false,false,false,false,true >,
                         cudaFuncAttributeMaxDynamicSharedMemorySize, SMEM_BYTES);

    const int nW1 = NL * DMLP * DD;
    split_f32<<<(nW1 + 255) / 256, 256>>>(W1, w1h, w1l, nW1);
    split_f32<<<(nW1 + 255) / 256, 256>>>(W2, w2h, w2l, nW1);
    split_f32<<<(DOUT * DD + 255) / 256, 256>>>(Wout, woh, wol, DOUT * DD);
    pack_qkv_w<<<(NL * NQKV * 128 + 255) / 256, 256>>>(Wq, Wk, Wv);
    pack_qkv_b<<<(NL * NQKV + 255) / 256, 256>>>(bq, bk, bv);

    patch_embed_kernel<<<dim3(6, NBC), 128>>>(batch, Wp, bp, pos);

    const dim3 gQ(NQKV / BN, NT / BM);
    const dim3 g1(DMLP / BN, NT / BM);
    const dim3 g2(DD / BN, NT / BM);
    const dim3 gO(DOUT / BN, NT / BM);

    for (int l = 0; l < NL; l++) {
        ln_split<<<NT, 256>>>(zp, hh, hl, ln1g + l * 768, ln1b + l * 768);
        gemm_bf16<false,false,true,false,true><<<gQ, 256, SMEM_BYTES>>>(
            hh, hl, 768, wqh + (size_t)l * NQKV * 128, wql + (size_t)l * NQKV * 128, 128,
            bpp + l * NQKV, nullptr, nullptr, qkvp, nullptr, nullptr, NQKV, 128);
        attn_kernel<<<dim3(NBC, NH), 256>>>();
        ln_split<<<NT, 256>>>(zp, hh, hl, ln2g + l * 768, ln2b + l * 768);
        gemm_bf16<true,false,false,true,false><<<g1, 256, SMEM_BYTES>>>(
            hh, hl, 768, w1h + (size_t)l * DMLP * DD, w1l + (size_t)l * DMLP * DD, 768,
            b1 + l * DMLP, nullptr, nullptr, nullptr, mh, ml, DMLP, 768);
        gemm_bf16<false,true,false,false,true><<<g2, 256, SMEM_BYTES>>>(
            mh, ml, 1536, w2h + (size_t)l * DD * DMLP, w2l + (size_t)l * DD * DMLP, 1536,
            b2 + l * 768, hh, hl, zp, nullptr, nullptr, DD, 1536);
    }

    split_f32<<<(NT * DD + 255) / 256, 256>>>(zp, hh, hl, NT * DD);
    gemm_bf16<false,false,false,false,true><<<gO, 256, SMEM_BYTES>>>(
        hh, hl, 768, woh, wol, 768, bout, nullptr, nullptr,
        (float*)d_out, nullptr, nullptr, DOUT, 768);
}

// round 15
// speedup vs baseline: 2.5249x; 1.2266x over previous
#include <cuda_runtime.h>
#include <cuda_fp16.h>
#include <cstdint>

// ---------------------------------------------------------------------------
// FeatureExtractorViT (B=512,C=3,IMG=36,PS=6,S=36,D=768,H=12,HD=64,L=4,OUT=256)
// NT = 55296 tokens.  GEMMs via mma.sync fp16 (HMMA) 2-pass:
//   A = Ah + Al (two fp16 halves, ~22 mantissa bits), B = weights in single
//   rn fp16.  C = Ah*Bh + Al*Bh, fp32 accumulate.  Expected rel_err ~3e-4.
// ---------------------------------------------------------------------------

#define NT    55296
#define DD    768
#define NBC   1536
#define NH    12
#define NL    4
#define DOUT  256
#define DMLP  1536
#define NQKV  2304

// GEMM tiling
#define BM 256
#define BN 128
#define BK 32               // fp32 k per chunk (A cols: hi 0..31, lo 32..63)
#define KS 72               // A smem row stride (fp16), conflict-free
#define KSB 40              // B smem row stride (fp16), conflict-free
#define ASZ (BM * KS * 2)   // 36864 B per A buffer
#define BSZ (BN * KSB * 2)  // 10240 B per B buffer
#define SMEM_BYTES (2 * ASZ + 2 * BSZ)   // 94208

// ---------------- scratch (device globals; no runtime alloc) ---------------
static __device__ float    g_z[(size_t)NT * DD];       // residual stream (fp32)
static __device__ float    g_qkv[(size_t)NT * NQKV];   // q|k|v (fp32)
static __device__ uint16_t g_hh[(size_t)NT * DD];      // LN out hi (fp16 bits)
static __device__ uint16_t g_hl[(size_t)NT * DD];      // LN out lo
static __device__ uint16_t g_mh[(size_t)NT * DMLP];    // MLP hidden hi
static __device__ uint16_t g_ml[(size_t)NT * DMLP];    // MLP hidden lo
static __device__ uint16_t g_w1[(size_t)NL * DMLP * DD];   // weights fp16
static __device__ uint16_t g_w2[(size_t)NL * DD * DMLP];
static __device__ uint16_t g_wq[(size_t)NL * NQKV * 128];  // packed QKV fp16
static __device__ uint16_t g_wo[(size_t)DOUT * DD];
static __device__ float    g_bp[(size_t)NL * NQKV];

// ---------------------------- helpers --------------------------------------
__device__ __forceinline__ uint32_t smem_u32(const void* p) {
    uint32_t a;
    asm("{ .reg .u64 t; cvta.to.shared.u64 t, %1; cvt.u32.u64 %0, t; }"
        : "=r"(a) : "l"(p));
    return a;
}
__device__ __forceinline__ float h2f(uint16_t b) {
    return __half2float(__ushort_as_half(b));
}
__device__ __forceinline__ void split1(float x, uint16_t& h, uint16_t& l) {
    __half hb = __float2half_rn(x);
    h = __half_as_ushort(hb);
    l = __half_as_ushort(__float2half_rn(x - __half2float(hb)));
}
__device__ __forceinline__ void mma16816(float& d0, float& d1, float& d2, float& d3,
                                         uint32_t a0, uint32_t a1, uint32_t a2,
                                         uint32_t a3, uint32_t b0, uint32_t b1) {
    asm("mma.sync.aligned.m16n8k16.row.col.f32.f16.f16.f32 "
        "{%0,%1,%2,%3}, {%4,%5,%6,%7}, {%8,%9}, {%0,%1,%2,%3};"
        : "+f"(d0), "+f"(d1), "+f"(d2), "+f"(d3)
        : "r"(a0), "r"(a1), "r"(a2), "r"(a3), "r"(b0), "r"(b1));
}
__device__ __forceinline__ void ldsm4(uint32_t& r0, uint32_t& r1, uint32_t& r2,
                                      uint32_t& r3, uint32_t addr) {
    asm volatile("ldmatrix.sync.aligned.m8n8.x4.shared.b16 {%0,%1,%2,%3}, [%4];"
                 : "=r"(r0), "=r"(r1), "=r"(r2), "=r"(r3) : "r"(addr));
}
#define CP16(dst, src) \
    asm volatile("cp.async.ca.shared.global [%0], [%1], 16;" :: "r"(dst), "l"(src))
#define CP_COMMIT() asm volatile("cp.async.commit_group;" ::: "memory")
#define CP_WAIT(n)  asm volatile("cp.async.wait_group %0;" :: "n"(n) : "memory")

// ---------------------- GEMM: C = A @ B^T (+bias,+relu,+res) ---------------
// A: [M,K] as fp16 hi/lo (lda);  B: [N,K] single fp16 (ldb).
// C = Ah*Bh + Al*Bh (fp32 acc).  Tile 256x128, 8 warps (4x2), warp 64x64.
template <bool RELU, bool RES, bool QKV, bool OSPLIT, bool OF32>
__global__ void __launch_bounds__(256)
gemm_fp16(const uint16_t* __restrict__ Ahi, const uint16_t* __restrict__ Alo, int lda,
          const uint16_t* __restrict__ Bw, int ldb,
          const float* __restrict__ bias,
          const uint16_t* __restrict__ reshi, const uint16_t* __restrict__ reslo,
          float* __restrict__ C, uint16_t* __restrict__ Chi, uint16_t* __restrict__ Clo,
          int N, int K)
{
    extern __shared__ __align__(16) unsigned char dsm[];
    const int t = threadIdx.x;
    const int lane = t & 31, wid = t >> 5;
    const int wm = wid & 3, wn = wid >> 2;           // 4x2 warp grid
    const int n0 = blockIdx.x * BN;
    const int m0 = blockIdx.y * BM;
    const int acol0 = QKV ? (n0 % 768) : 0;          // QKV K-window
    const uint32_t sA0 = smem_u32(dsm);
    const uint32_t sB0 = sA0 + 2 * ASZ;

    float acc[4][8][4];
#pragma unroll
    for (int i = 0; i < 4; i++)
#pragma unroll
        for (int j = 0; j < 8; j++)
#pragma unroll
            for (int q = 0; q < 4; q++) acc[i][j][q] = 0.f;

    auto load_chunk = [&](int ck, int buf) {
        const int kb = acol0 + ck * BK;
#pragma unroll
        for (int i = 0; i < 8; i++) {                 // A: 2048 16B segs
            int seg = t + i * 256;
            int row = seg >> 3, part = seg & 7;
            int kk = (part & 3) * 8;
            const uint16_t* src = ((part < 4) ? Ahi : Alo) +
                                  (size_t)(m0 + row) * lda + kb + kk;
            uint32_t dst = sA0 + buf * ASZ +
                           (uint32_t)(row * KS + ((part < 4) ? 0 : 32) + kk) * 2;
            CP16(dst, src);
        }
        const int kb2 = ck * BK;
#pragma unroll
        for (int i = 0; i < 2; i++) {                 // B: 512 16B segs
            int seg = t + i * 256;
            int row = seg >> 2, part = seg & 3;
            int kk = part * 8;
            const uint16_t* src = Bw + (size_t)(n0 + row) * ldb + kb2 + kk;
            uint32_t dst = sB0 + buf * BSZ + (uint32_t)(row * KSB + kk) * 2;
            CP16(dst, src);
        }
    };

    // ldmatrix per-lane addresses.
    const int aRow = (lane & 7) + ((lane >> 3) & 1) * 8;
    const int aCol = (lane >> 4) * 8;
    const uint32_t aAddr = sA0 + (uint32_t)((wm * 64 + aRow) * KS + aCol) * 2;
    const int bRow = (lane & 7) + (lane >> 4) * 8;
    const int bCol = ((lane >> 3) & 1) * 8;
    const uint32_t bAddr = sB0 + (uint32_t)((wn * 64 + bRow) * KSB + bCol) * 2;

    const int nck = K >> 5;
    load_chunk(0, 0); CP_COMMIT();

    for (int ck = 0; ck < nck; ck++) {
        const int buf = ck & 1;
        if (ck + 1 < nck) { load_chunk(ck + 1, buf ^ 1); CP_COMMIT(); CP_WAIT(1); }
        else              { CP_WAIT(0); }
        __syncthreads();
        const uint32_t aB = aAddr + buf * ASZ;
        const uint32_t bB = bAddr + buf * BSZ;
#pragma unroll
        for (int ko = 0; ko < 32; ko += 16) {
            uint32_t ah[4][4], al[4][4], bb[4][4];
#pragma unroll
            for (int mt = 0; mt < 4; mt++)
                ldsm4(ah[mt][0], ah[mt][1], ah[mt][2], ah[mt][3],
                      aB + (uint32_t)(mt * 16 * KS + ko) * 2);
#pragma unroll
            for (int mt = 0; mt < 4; mt++)
                ldsm4(al[mt][0], al[mt][1], al[mt][2], al[mt][3],
                      aB + (uint32_t)(mt * 16 * KS + ko + 32) * 2);
#pragma unroll
            for (int p = 0; p < 4; p++)        // B (2 n-tiles per x4)
                ldsm4(bb[p][0], bb[p][1], bb[p][2], bb[p][3],
                      bB + (uint32_t)(p * 16 * KSB + ko) * 2);
            // Ah * B
#pragma unroll
            for (int mt = 0; mt < 4; mt++)
#pragma unroll
                for (int p = 0; p < 4; p++) {
                    mma16816(acc[mt][2*p][0], acc[mt][2*p][1], acc[mt][2*p][2], acc[mt][2*p][3],
                             ah[mt][0], ah[mt][1], ah[mt][2], ah[mt][3], bb[p][0], bb[p][1]);
                    mma16816(acc[mt][2*p+1][0], acc[mt][2*p+1][1], acc[mt][2*p+1][2], acc[mt][2*p+1][3],
                             ah[mt][0], ah[mt][1], ah[mt][2], ah[mt][3], bb[p][2], bb[p][3]);
                }
            // Al * B  (B frags reused)
#pragma unroll
            for (int mt = 0; mt < 4; mt++)
#pragma unroll
                for (int p = 0; p < 4; p++) {
                    mma16816(acc[mt][2*p][0], acc[mt][2*p][1], acc[mt][2*p][2], acc[mt][2*p][3],
                             al[mt][0], al[mt][1], al[mt][2], al[mt][3], bb[p][0], bb[p][1]);
                    mma16816(acc[mt][2*p+1][0], acc[mt][2*p+1][1], acc[mt][2*p+1][2], acc[mt][2*p+1][3],
                             al[mt][0], al[mt][1], al[mt][2], al[mt][3], bb[p][2], bb[p][3]);
                }
        }
        __syncthreads();
    }

    // epilogue
#pragma unroll
    for (int nt = 0; nt < 8; nt++) {
        const int c0 = n0 + wn * 64 + nt * 8 + (lane & 3) * 2;
        const float b0 = bias[c0], b1v = bias[c0 + 1];
#pragma unroll
        for (int mt = 0; mt < 4; mt++) {
            const int r0 = m0 + wm * 64 + mt * 16 + (lane >> 2);
#pragma unroll
            for (int half = 0; half < 2; half++) {
                const int r = r0 + half * 8;
                float v0 = acc[mt][nt][half * 2 + 0] + b0;
                float v1 = acc[mt][nt][half * 2 + 1] + b1v;
                if (RELU) { v0 = fmaxf(v0, 0.f); v1 = fmaxf(v1, 0.f); }
                const size_t off = (size_t)r * N + c0;
                if (RES) {
                    v0 += h2f(reshi[off])     + h2f(reslo[off]);
                    v1 += h2f(reshi[off + 1]) + h2f(reslo[off + 1]);
                }
                if (OF32) {
                    float2 o; o.x = v0; o.y = v1;
                    *(float2*)(C + off) = o;
                }
                if (OSPLIT) {
                    uint16_t h0, l0, h1, l1;
                    split1(v0, h0, l0); split1(v1, h1, l1);
                    *(uint32_t*)(Chi + off) = ((uint32_t)h1 << 16) | h0;
                    *(uint32_t*)(Clo + off) = ((uint32_t)l1 << 16) | l0;
                }
            }
        }
    }
}

// --------------------- weight conversion / packing -------------------------
__global__ void conv_f16(const float* __restrict__ src, uint16_t* __restrict__ dst,
                         int n)
{
    int i = blockIdx.x * 256 + threadIdx.x;
    if (i < n) dst[i] = __half_as_ushort(__float2half_rn(src[i]));
}
__global__ void split_f16(const float* __restrict__ src, uint16_t* __restrict__ hi,
                          uint16_t* __restrict__ lo, int n)
{
    int i = blockIdx.x * 256 + threadIdx.x;
    if (i < n) { uint16_t h, l; split1(src[i], h, l); hi[i] = h; lo[i] = l; }
}

__global__ void pack_qkv_w(const float* __restrict__ Wq, const float* __restrict__ Wk,
                           const float* __restrict__ Wv)
{
    int idx = blockIdx.x * 256 + threadIdx.x;
    if (idx >= NL * NQKV * 128) return;
    int l = idx / (NQKV * 128);
    int rem = idx % (NQKV * 128);
    int c = rem / 128, kk = rem % 128;
    int mat = c / 768, cw = c % 768;
    int h = cw / 64, e = cw % 64;
    int kwin = (cw / 128) * 128;
    int d = kwin + kk - h * 64;
    float val = 0.f;
    if (d >= 0 && d < 64) {
        const float* W = (mat == 0) ? Wq : (mat == 1 ? Wk : Wv);
        val = W[(((size_t)l * NH + h) * 64 + e) * 64 + d];
    }
    g_wq[idx] = __half_as_ushort(__float2half_rn(val));
}
__global__ void pack_qkv_b(const float* __restrict__ bq, const float* __restrict__ bk,
                           const float* __restrict__ bv)
{
    int idx = blockIdx.x * 256 + threadIdx.x;
    if (idx >= NL * NQKV) return;
    int l = idx / NQKV, c = idx % NQKV;
    int mat = c / 768, cw = c % 768;
    int h = cw / 64, e = cw % 64;
    const float* b = (mat == 0) ? bq : (mat == 1 ? bk : bv);
    g_bp[idx] = b[((size_t)l * NH + h) * 64 + e];
}

// ---------------------------- patch embed ----------------------------------
__global__ void patch_embed_kernel(const float* __restrict__ batch,
                                   const float* __restrict__ Wp,
                                   const float* __restrict__ bp,
                                   const float* __restrict__ pos)
{
    __shared__ float px[36 * 36];
    __shared__ float Ws[128 * 36];
    const int bc = blockIdx.y, d0 = blockIdx.x * 128, t = threadIdx.x;
    const float* img = batch + bc * 1296;
    for (int e = t; e < 1296; e += 128) {
        int row = e / 36, col = e - row * 36;
        int s = (row / 6) * 6 + (col / 6);
        int p = (row % 6) * 6 + (col % 6);
        px[s * 36 + p] = img[e];
    }
    for (int i = t; i < 128 * 36; i += 128) Ws[i] = Wp[d0 * 36 + i];
    __syncthreads();
    const int d = d0 + t;
    float w[36];
#pragma unroll
    for (int p = 0; p < 36; p++) w[p] = Ws[t * 36 + p];
    const float bias = bp[d];
    for (int s = 0; s < 36; s++) {
        float acc = bias + pos[s * 768 + d];
        const float* pr = &px[s * 36];
#pragma unroll
        for (int p = 0; p < 36; p++) acc = fmaf(pr[p], w[p], acc);
        g_z[(size_t)(bc * 36 + s) * 768 + d] = acc;
    }
}

// ------------------------ LayerNorm -> hi/lo fp16 --------------------------
__global__ void ln_split(const float* __restrict__ in, uint16_t* __restrict__ hi,
                         uint16_t* __restrict__ lo, const float* __restrict__ gamma,
                         const float* __restrict__ beta)
{
    const int row = blockIdx.x;
    const float* x = in + (size_t)row * 768;
    const int t = threadIdx.x;
    float v0 = x[t], v1 = x[t + 256], v2 = x[t + 512];
    float s = v0 + v1 + v2;
    float q = v0 * v0 + v1 * v1 + v2 * v2;
#pragma unroll
    for (int o = 16; o > 0; o >>= 1) {
        s += __shfl_xor_sync(0xffffffffu, s, o);
        q += __shfl_xor_sync(0xffffffffu, q, o);
    }
    __shared__ float rs[8], rq[8];
    __shared__ float smean, srstd;
    if ((t & 31) == 0) { rs[t >> 5] = s; rq[t >> 5] = q; }
    __syncthreads();
    if (t == 0) {
        float S = 0.f, Q = 0.f;
#pragma unroll
        for (int i = 0; i < 8; i++) { S += rs[i]; Q += rq[i]; }
        float m = S * (1.0f / 768.0f);
        float var = Q * (1.0f / 768.0f) - m * m;
        smean = m; srstd = rsqrtf(var + 1e-5f);
    }
    __syncthreads();
    const float m = smean, r = srstd;
    const size_t base = (size_t)row * 768;
    float y0 = (v0 - m) * r * gamma[t]       + beta[t];
    float y1 = (v1 - m) * r * gamma[t + 256] + beta[t + 256];
    float y2 = (v2 - m) * r * gamma[t + 512] + beta[t + 512];
    uint16_t h, l;
    split1(y0, h, l); hi[base + t]       = h; lo[base + t]       = l;
    split1(y1, h, l); hi[base + t + 256] = h; lo[base + t + 256] = l;
    split1(y2, h, l); hi[base + t + 512] = h; lo[base + t + 512] = l;
}

// ---------------------------- attention ------------------------------------
#define QK_STRIDE 67
#define V_STRIDE  66
__global__ void __launch_bounds__(256) attn_kernel()
{
    __shared__ float Qs[36 * QK_STRIDE], Ks[36 * QK_STRIDE];
    __shared__ float Vs[36 * V_STRIDE];
    __shared__ float P[36 * 40];
    const int bc = blockIdx.x, h = blockIdx.y, t = threadIdx.x;
    const size_t qbase = (size_t)bc * 36 * NQKV + h * 64;

    for (int idx = t; idx < 2304; idx += 256) {
        int s = idx >> 6, e = idx & 63;
        size_t g = qbase + (size_t)s * NQKV + e;
        Qs[s * QK_STRIDE + e] = g_qkv[g] * 0.125f;   // fold 1/sqrt(64)
        Ks[s * QK_STRIDE + e] = g_qkv[g + 768];
        Vs[s * V_STRIDE  + e] = g_qkv[g + 1536];
    }
    __syncthreads();

    for (int vt = t; vt < 324; vt += 256) {      // 18x18 of 2x2 score tiles
        int i0 = (vt / 18) * 2, j0 = (vt % 18) * 2;
        const float* q0 = &Qs[i0 * QK_STRIDE]; const float* q1 = q0 + QK_STRIDE;
        const float* k0 = &Ks[j0 * QK_STRIDE]; const float* k1 = k0 + QK_STRIDE;
        float a00 = 0.f, a01 = 0.f, a10 = 0.f, a11 = 0.f;
#pragma unroll
        for (int e = 0; e < 64; e++) {
            float qa = q0[e], qb = q1[e], ka = k0[e], kb = k1[e];
            a00 = fmaf(qa, ka, a00); a01 = fmaf(qa, kb, a01);
            a10 = fmaf(qb, ka, a10); a11 = fmaf(qb, kb, a11);
        }
        P[i0 * 40 + j0]           = a00;
        P[i0 * 40 + j0 + 1]       = a01;
        P[(i0 + 1) * 40 + j0]     = a10;
        P[(i0 + 1) * 40 + j0 + 1] = a11;
    }
    __syncthreads();

    if (t < 36) {
        float mx = -1e30f;
        for (int j = 0; j < 36; j++) mx = fmaxf(mx, P[t * 40 + j]);
        float sum = 0.f;
        for (int j = 0; j < 36; j++) {
            float ex = expf(P[t * 40 + j] - mx);
            P[t * 40 + j] = ex;
            sum += ex;
        }
        float inv = 1.f / sum;
        for (int j = 0; j < 36; j++) P[t * 40 + j] *= inv;
    }
    __syncthreads();

    float* zr = g_z + (size_t)bc * 36 * 768 + h * 64;
    for (int vt = t; vt < 576; vt += 256) {      // 18 rows x 32 col pairs
        int i0 = (vt / 32) * 2, e0 = (vt % 32) * 2;
        const float* p0 = &P[i0 * 40]; const float* p1 = p0 + 40;
        float a00 = 0.f, a01 = 0.f, a10 = 0.f, a11 = 0.f;
#pragma unroll
        for (int j = 0; j < 36; j++) {
            float2 v = *(const float2*)&Vs[j * V_STRIDE + e0];
            float w0 = p0[j], w1 = p1[j];
            a00 = fmaf(w0, v.x, a00); a01 = fmaf(w0, v.y, a01);
            a10 = fmaf(w1, v.x, a10); a11 = fmaf(w1, v.y, a11);
        }
        float* z0 = zr + (size_t)i0 * 768 + e0;
        z0[0]   += a00; z0[1]   += a01;
        z0[768] += a10; z0[769] += a11;
    }
}

// ------------------------------- launch ------------------------------------
extern "C" void kernel_launch(void* const* d_in, const int* in_sizes, int n_in,
                              void* d_out, int out_size)
{
    (void)in_sizes; (void)n_in; (void)out_size;
    const float* batch = (const float*)d_in[0];
    const float* Wp    = (const float*)d_in[1];
    const float* bp    = (const float*)d_in[2];
    const float* pos   = (const float*)d_in[3];
    const float* ln1g  = (const float*)d_in[4];
    const float* ln1b  = (const float*)d_in[5];
    const float* Wq    = (const float*)d_in[6];
    const float* bq    = (const float*)d_in[7];
    const float* Wk    = (const float*)d_in[8];
    const float* bk    = (const float*)d_in[9];
    const float* Wv    = (const float*)d_in[10];
    const float* bv    = (const float*)d_in[11];
    const float* ln2g  = (const float*)d_in[12];
    const float* ln2b  = (const float*)d_in[13];
    const float* W1    = (const float*)d_in[14];
    const float* b1    = (const float*)d_in[15];
    const float* W2    = (const float*)d_in[16];
    const float* b2    = (const float*)d_in[17];
    const float* Wout  = (const float*)d_in[18];
    const float* bout  = (const float*)d_in[19];

    float *zp, *qkvp, *bpp;
    uint16_t *hh, *hl, *mh, *ml, *w1p, *w2p, *wqp, *wop;
    cudaGetSymbolAddress((void**)&zp,   g_z);
    cudaGetSymbolAddress((void**)&qkvp, g_qkv);
    cudaGetSymbolAddress((void**)&bpp,  g_bp);
    cudaGetSymbolAddress((void**)&hh,   g_hh);
    cudaGetSymbolAddress((void**)&hl,   g_hl);
    cudaGetSymbolAddress((void**)&mh,   g_mh);
    cudaGetSymbolAddress((void**)&ml,   g_ml);
    cudaGetSymbolAddress((void**)&w1p,  g_w1);
    cudaGetSymbolAddress((void**)&w2p,  g_w2);
    cudaGetSymbolAddress((void**)&wqp,  g_wq);
    cudaGetSymbolAddress((void**)&wop,  g_wo);

    cudaFuncSetAttribute(gemm_fp16<false,false,true ,false,true >,
                         cudaFuncAttributeMaxDynamicSharedMemorySize, SMEM_BYTES);
    cudaFuncSetAttribute(gemm_fp16<true ,false,false,true ,false>,
                         cudaFuncAttributeMaxDynamicSharedMemorySize, SMEM_BYTES);
    cudaFuncSetAttribute(gemm_fp16<false,true ,false,false,true >,
                         cudaFuncAttributeMaxDynamicSharedMemorySize, SMEM_BYTES);
    cudaFuncSetAttribute(gemm_fp16<false,false,false,false,true >,
                         cudaFuncAttributeMaxDynamicSharedMemorySize, SMEM_BYTES);

    const int nW1 = NL * DMLP * DD;
    conv_f16<<<(nW1 + 255) / 256, 256>>>(W1, w1p, nW1);
    conv_f16<<<(nW1 + 255) / 256, 256>>>(W2, w2p, nW1);
    conv_f16<<<(DOUT * DD + 255) / 256, 256>>>(Wout, wop, DOUT * DD);
    pack_qkv_w<<<(NL * NQKV * 128 + 255) / 256, 256>>>(Wq, Wk, Wv);
    pack_qkv_b<<<(NL * NQKV + 255) / 256, 256>>>(bq, bk, bv);

    patch_embed_kernel<<<dim3(6, NBC), 128>>>(batch, Wp, bp, pos);

    const dim3 gQ(NQKV / BN, NT / BM);
    const dim3 g1(DMLP / BN, NT / BM);
    const dim3 g2(DD / BN, NT / BM);
    const dim3 gO(DOUT / BN, NT / BM);

    for (int l = 0; l < NL; l++) {
        ln_split<<<NT, 256>>>(zp, hh, hl, ln1g + l * 768, ln1b + l * 768);
        gemm_fp16<false,false,true,false,true><<<gQ, 256, SMEM_BYTES>>>(
            hh, hl, 768, wqp + (size_t)l * NQKV * 128, 128,
            bpp + l * NQKV, nullptr, nullptr, qkvp, nullptr, nullptr, NQKV, 128);
        attn_kernel<<<dim3(NBC, NH), 256>>>();
        ln_split<<<NT, 256>>>(zp, hh, hl, ln2g + l * 768, ln2b + l * 768);
        gemm_fp16<true,false,false,true,false><<<g1, 256, SMEM_BYTES>>>(
            hh, hl, 768, w1p + (size_t)l * DMLP * DD, 768,
            b1 + l * DMLP, nullptr, nullptr, nullptr, mh, ml, DMLP, 768);
        gemm_fp16<false,true,false,false,true><<<g2, 256, SMEM_BYTES>>>(
            mh, ml, 1536, w2p + (size_t)l * DD * DMLP, 1536,
            b2 + l * 768, hh, hl, zp, nullptr, nullptr, DD, 1536);
    }

    split_f16<<<(NT * DD + 255) / 256, 256>>>(zp, hh, hl, NT * DD);
    gemm_fp16<false,false,false,false,true><<<gO, 256, SMEM_BYTES>>>(
        hh, hl, 768, wop, 768, bout, nullptr, nullptr,
        (float*)d_out, nullptr, nullptr, DOUT, 768);
}

// round 16
// speedup vs baseline: 3.4100x; 1.3505x over previous
#include <cuda_runtime.h>
#include <cuda_fp16.h>
#include <cstdint>

// ---------------------------------------------------------------------------
// FeatureExtractorViT (B=512,C=3,IMG=36,PS=6,S=36,D=768,H=12,HD=64,L=4,OUT=256)
// NT = 55296 tokens.  GEMMs via mma.sync fp16 (HMMA) SINGLE pass:
//   A rn fp16, B rn fp16, fp32 accumulate.  Residual stream kept fp32;
//   LN2 residual reconstructed from fp16 hi+lo.  Expected rel_err ~6e-4.
// ---------------------------------------------------------------------------

#define NT    55296
#define DD    768
#define NBC   1536
#define NH    12
#define NL    4
#define DOUT  256
#define DMLP  1536
#define NQKV  2304

// GEMM tiling
#define BM 256
#define BN 128
#define BK 32               // fp32 k per chunk
#define KSA 40              // A smem row stride (fp16), conflict-free (80B)
#define KSB 40              // B smem row stride
#define ASZ (BM * KSA * 2)  // 20480 B per A buffer
#define BSZ (BN * KSB * 2)  // 10240 B per B buffer
#define SMEM_BYTES (2 * ASZ + 2 * BSZ)   // 61440

// ---------------- scratch (device globals; no runtime alloc) ---------------
static __device__ float    g_z[(size_t)NT * DD];       // residual stream (fp32)
static __device__ float    g_qkv[(size_t)NT * NQKV];   // q|k|v (fp32)
static __device__ uint16_t g_hh[(size_t)NT * DD];      // LN out hi (fp16 bits)
static __device__ uint16_t g_hl[(size_t)NT * DD];      // LN out lo (residual only)
static __device__ uint16_t g_mh[(size_t)NT * DMLP];    // MLP hidden (fp16)
static __device__ uint16_t g_w1[(size_t)NL * DMLP * DD];   // weights fp16
static __device__ uint16_t g_w2[(size_t)NL * DD * DMLP];
static __device__ uint16_t g_wq[(size_t)NL * NQKV * 128];  // packed QKV fp16
static __device__ uint16_t g_wo[(size_t)DOUT * DD];
static __device__ float    g_bp[(size_t)NL * NQKV];

// ---------------------------- helpers --------------------------------------
__device__ __forceinline__ uint32_t smem_u32(const void* p) {
    uint32_t a;
    asm("{ .reg .u64 t; cvta.to.shared.u64 t, %1; cvt.u32.u64 %0, t; }"
        : "=r"(a) : "l"(p));
    return a;
}
__device__ __forceinline__ float h2f(uint16_t b) {
    return __half2float(__ushort_as_half(b));
}
__device__ __forceinline__ void split1(float x, uint16_t& h, uint16_t& l) {
    __half hb = __float2half_rn(x);
    h = __half_as_ushort(hb);
    l = __half_as_ushort(__float2half_rn(x - __half2float(hb)));
}
__device__ __forceinline__ void mma16816(float& d0, float& d1, float& d2, float& d3,
                                         uint32_t a0, uint32_t a1, uint32_t a2,
                                         uint32_t a3, uint32_t b0, uint32_t b1) {
    asm("mma.sync.aligned.m16n8k16.row.col.f32.f16.f16.f32 "
        "{%0,%1,%2,%3}, {%4,%5,%6,%7}, {%8,%9}, {%0,%1,%2,%3};"
        : "+f"(d0), "+f"(d1), "+f"(d2), "+f"(d3)
        : "r"(a0), "r"(a1), "r"(a2), "r"(a3), "r"(b0), "r"(b1));
}
__device__ __forceinline__ void ldsm4(uint32_t& r0, uint32_t& r1, uint32_t& r2,
                                      uint32_t& r3, uint32_t addr) {
    asm volatile("ldmatrix.sync.aligned.m8n8.x4.shared.b16 {%0,%1,%2,%3}, [%4];"
                 : "=r"(r0), "=r"(r1), "=r"(r2), "=r"(r3) : "r"(addr));
}
#define CP16(dst, src) \
    asm volatile("cp.async.ca.shared.global [%0], [%1], 16;" :: "r"(dst), "l"(src))
#define CP_COMMIT() asm volatile("cp.async.commit_group;" ::: "memory")
#define CP_WAIT(n)  asm volatile("cp.async.wait_group %0;" :: "n"(n) : "memory")

// ---------------------- GEMM: C = A @ B^T (+bias,+relu,+res) ---------------
// A: [M,K] fp16 (lda);  B: [N,K] fp16 (ldb).  fp32 accumulate.
// Tile 256x128, 8 warps (4x2), warp 64x64.  Double-buffered cp.async.
template <bool RELU, bool RES, bool QKV, bool OH16, bool OF32>
__global__ void __launch_bounds__(256)
gemm_fp16(const uint16_t* __restrict__ Aw, int lda,
          const uint16_t* __restrict__ Bw, int ldb,
          const float* __restrict__ bias,
          const uint16_t* __restrict__ reshi, const uint16_t* __restrict__ reslo,
          float* __restrict__ C, uint16_t* __restrict__ Ch,
          int N, int K)
{
    extern __shared__ __align__(16) unsigned char dsm[];
    const int t = threadIdx.x;
    const int lane = t & 31, wid = t >> 5;
    const int wm = wid & 3, wn = wid >> 2;           // 4x2 warp grid
    const int n0 = blockIdx.x * BN;
    const int m0 = blockIdx.y * BM;
    const int acol0 = QKV ? (n0 % 768) : 0;          // QKV K-window
    const uint32_t sA0 = smem_u32(dsm);
    const uint32_t sB0 = sA0 + 2 * ASZ;

    float acc[4][8][4];
#pragma unroll
    for (int i = 0; i < 4; i++)
#pragma unroll
        for (int j = 0; j < 8; j++)
#pragma unroll
            for (int q = 0; q < 4; q++) acc[i][j][q] = 0.f;

    auto load_chunk = [&](int ck, int buf) {
        const int kb = acol0 + ck * BK;
#pragma unroll
        for (int i = 0; i < 4; i++) {                 // A: 1024 16B segs
            int seg = t + i * 256;
            int row = seg >> 2, part = seg & 3;
            int kk = part * 8;
            const uint16_t* src = Aw + (size_t)(m0 + row) * lda + kb + kk;
            uint32_t dst = sA0 + buf * ASZ + (uint32_t)(row * KSA + kk) * 2;
            CP16(dst, src);
        }
        const int kb2 = ck * BK;
#pragma unroll
        for (int i = 0; i < 2; i++) {                 // B: 512 16B segs
            int seg = t + i * 256;
            int row = seg >> 2, part = seg & 3;
            int kk = part * 8;
            const uint16_t* src = Bw + (size_t)(n0 + row) * ldb + kb2 + kk;
            uint32_t dst = sB0 + buf * BSZ + (uint32_t)(row * KSB + kk) * 2;
            CP16(dst, src);
        }
    };

    // ldmatrix per-lane addresses.
    const int aRow = (lane & 7) + ((lane >> 3) & 1) * 8;
    const int aCol = (lane >> 4) * 8;
    const uint32_t aAddr = sA0 + (uint32_t)((wm * 64 + aRow) * KSA + aCol) * 2;
    const int bRow = (lane & 7) + (lane >> 4) * 8;
    const int bCol = ((lane >> 3) & 1) * 8;
    const uint32_t bAddr = sB0 + (uint32_t)((wn * 64 + bRow) * KSB + bCol) * 2;

    const int nck = K >> 5;
    load_chunk(0, 0); CP_COMMIT();

    for (int ck = 0; ck < nck; ck++) {
        const int buf = ck & 1;
        if (ck + 1 < nck) { load_chunk(ck + 1, buf ^ 1); CP_COMMIT(); CP_WAIT(1); }
        else              { CP_WAIT(0); }
        __syncthreads();
        const uint32_t aB = aAddr + buf * ASZ;
        const uint32_t bB = bAddr + buf * BSZ;
#pragma unroll
        for (int ko = 0; ko < 32; ko += 16) {
            uint32_t aa[4][4], bb[4][4];
#pragma unroll
            for (int mt = 0; mt < 4; mt++)
                ldsm4(aa[mt][0], aa[mt][1], aa[mt][2], aa[mt][3],
                      aB + (uint32_t)(mt * 16 * KSA + ko) * 2);
#pragma unroll
            for (int p = 0; p < 4; p++)        // B (2 n-tiles per x4)
                ldsm4(bb[p][0], bb[p][1], bb[p][2], bb[p][3],
                      bB + (uint32_t)(p * 16 * KSB + ko) * 2);
#pragma unroll
            for (int mt = 0; mt < 4; mt++)
#pragma unroll
                for (int p = 0; p < 4; p++) {
                    mma16816(acc[mt][2*p][0], acc[mt][2*p][1], acc[mt][2*p][2], acc[mt][2*p][3],
                             aa[mt][0], aa[mt][1], aa[mt][2], aa[mt][3], bb[p][0], bb[p][1]);
                    mma16816(acc[mt][2*p+1][0], acc[mt][2*p+1][1], acc[mt][2*p+1][2], acc[mt][2*p+1][3],
                             aa[mt][0], aa[mt][1], aa[mt][2], aa[mt][3], bb[p][2], bb[p][3]);
                }
        }
        __syncthreads();
    }

    // epilogue
#pragma unroll
    for (int nt = 0; nt < 8; nt++) {
        const int c0 = n0 + wn * 64 + nt * 8 + (lane & 3) * 2;
        const float b0 = bias[c0], b1v = bias[c0 + 1];
#pragma unroll
        for (int mt = 0; mt < 4; mt++) {
            const int r0 = m0 + wm * 64 + mt * 16 + (lane >> 2);
#pragma unroll
            for (int half = 0; half < 2; half++) {
                const int r = r0 + half * 8;
                float v0 = acc[mt][nt][half * 2 + 0] + b0;
                float v1 = acc[mt][nt][half * 2 + 1] + b1v;
                if (RELU) { v0 = fmaxf(v0, 0.f); v1 = fmaxf(v1, 0.f); }
                const size_t off = (size_t)r * N + c0;
                if (RES) {
                    v0 += h2f(reshi[off])     + h2f(reslo[off]);
                    v1 += h2f(reshi[off + 1]) + h2f(reslo[off + 1]);
                }
                if (OF32) {
                    float2 o; o.x = v0; o.y = v1;
                    *(float2*)(C + off) = o;
                }
                if (OH16) {
                    uint32_t h0 = __half_as_ushort(__float2half_rn(v0));
                    uint32_t h1 = __half_as_ushort(__float2half_rn(v1));
                    *(uint32_t*)(Ch + off) = (h1 << 16) | h0;
                }
            }
        }
    }
}

// --------------------- weight conversion / packing -------------------------
__global__ void conv_f16(const float* __restrict__ src, uint16_t* __restrict__ dst,
                         int n)
{
    int i = blockIdx.x * 256 + threadIdx.x;
    if (i < n) dst[i] = __half_as_ushort(__float2half_rn(src[i]));
}

__global__ void pack_qkv_w(const float* __restrict__ Wq, const float* __restrict__ Wk,
                           const float* __restrict__ Wv)
{
    int idx = blockIdx.x * 256 + threadIdx.x;
    if (idx >= NL * NQKV * 128) return;
    int l = idx / (NQKV * 128);
    int rem = idx % (NQKV * 128);
    int c = rem / 128, kk = rem % 128;
    int mat = c / 768, cw = c % 768;
    int h = cw / 64, e = cw % 64;
    int kwin = (cw / 128) * 128;
    int d = kwin + kk - h * 64;
    float val = 0.f;
    if (d >= 0 && d < 64) {
        const float* W = (mat == 0) ? Wq : (mat == 1 ? Wk : Wv);
        val = W[(((size_t)l * NH + h) * 64 + e) * 64 + d];
    }
    g_wq[idx] = __half_as_ushort(__float2half_rn(val));
}
__global__ void pack_qkv_b(const float* __restrict__ bq, const float* __restrict__ bk,
                           const float* __restrict__ bv)
{
    int idx = blockIdx.x * 256 + threadIdx.x;
    if (idx >= NL * NQKV) return;
    int l = idx / NQKV, c = idx % NQKV;
    int mat = c / 768, cw = c % 768;
    int h = cw / 64, e = cw % 64;
    const float* b = (mat == 0) ? bq : (mat == 1 ? bk : bv);
    g_bp[idx] = b[((size_t)l * NH + h) * 64 + e];
}

// ---------------------------- patch embed ----------------------------------
__global__ void patch_embed_kernel(const float* __restrict__ batch,
                                   const float* __restrict__ Wp,
                                   const float* __restrict__ bp,
                                   const float* __restrict__ pos)
{
    __shared__ float px[36 * 36];
    __shared__ float Ws[128 * 36];
    const int bc = blockIdx.y, d0 = blockIdx.x * 128, t = threadIdx.x;
    const float* img = batch + bc * 1296;
    for (int e = t; e < 1296; e += 128) {
        int row = e / 36, col = e - row * 36;
        int s = (row / 6) * 6 + (col / 6);
        int p = (row % 6) * 6 + (col % 6);
        px[s * 36 + p] = img[e];
    }
    for (int i = t; i < 128 * 36; i += 128) Ws[i] = Wp[d0 * 36 + i];
    __syncthreads();
    const int d = d0 + t;
    float w[36];
#pragma unroll
    for (int p = 0; p < 36; p++) w[p] = Ws[t * 36 + p];
    const float bias = bp[d];
    for (int s = 0; s < 36; s++) {
        float acc = bias + pos[s * 768 + d];
        const float* pr = &px[s * 36];
#pragma unroll
        for (int p = 0; p < 36; p++) acc = fmaf(pr[p], w[p], acc);
        g_z[(size_t)(bc * 36 + s) * 768 + d] = acc;
    }
}

// ------------------------ LayerNorm -> fp16 hi(/lo) ------------------------
__global__ void ln_split(const float* __restrict__ in, uint16_t* __restrict__ hi,
                         uint16_t* __restrict__ lo, const float* __restrict__ gamma,
                         const float* __restrict__ beta)
{
    const int row = blockIdx.x;
    const float* x = in + (size_t)row * 768;
    const int t = threadIdx.x;
    float v0 = x[t], v1 = x[t + 256], v2 = x[t + 512];
    float s = v0 + v1 + v2;
    float q = v0 * v0 + v1 * v1 + v2 * v2;
#pragma unroll
    for (int o = 16; o > 0; o >>= 1) {
        s += __shfl_xor_sync(0xffffffffu, s, o);
        q += __shfl_xor_sync(0xffffffffu, q, o);
    }
    __shared__ float rs[8], rq[8];
    __shared__ float smean, srstd;
    if ((t & 31) == 0) { rs[t >> 5] = s; rq[t >> 5] = q; }
    __syncthreads();
    if (t == 0) {
        float S = 0.f, Q = 0.f;
#pragma unroll
        for (int i = 0; i < 8; i++) { S += rs[i]; Q += rq[i]; }
        float m = S * (1.0f / 768.0f);
        float var = Q * (1.0f / 768.0f) - m * m;
        smean = m; srstd = rsqrtf(var + 1e-5f);
    }
    __syncthreads();
    const float m = smean, r = srstd;
    const size_t base = (size_t)row * 768;
    float y0 = (v0 - m) * r * gamma[t]       + beta[t];
    float y1 = (v1 - m) * r * gamma[t + 256] + beta[t + 256];
    float y2 = (v2 - m) * r * gamma[t + 512] + beta[t + 512];
    uint16_t h, l;
    split1(y0, h, l); hi[base + t]       = h; lo[base + t]       = l;
    split1(y1, h, l); hi[base + t + 256] = h; lo[base + t + 256] = l;
    split1(y2, h, l); hi[base + t + 512] = h; lo[base + t + 512] = l;
}

// ---------------------------- attention ------------------------------------
#define QK_STRIDE 67
#define V_STRIDE  66
__global__ void __launch_bounds__(256) attn_kernel()
{
    __shared__ float Qs[36 * QK_STRIDE], Ks[36 * QK_STRIDE];
    __shared__ float Vs[36 * V_STRIDE];
    __shared__ float P[36 * 40];
    const int bc = blockIdx.x, h = blockIdx.y, t = threadIdx.x;
    const size_t qbase = (size_t)bc * 36 * NQKV + h * 64;

    for (int idx = t; idx < 2304; idx += 256) {
        int s = idx >> 6, e = idx & 63;
        size_t g = qbase + (size_t)s * NQKV + e;
        Qs[s * QK_STRIDE + e] = g_qkv[g] * 0.125f;   // fold 1/sqrt(64)
        Ks[s * QK_STRIDE + e] = g_qkv[g + 768];
        Vs[s * V_STRIDE  + e] = g_qkv[g + 1536];
    }
    __syncthreads();

    for (int vt = t; vt < 324; vt += 256) {      // 18x18 of 2x2 score tiles
        int i0 = (vt / 18) * 2, j0 = (vt % 18) * 2;
        const float* q0 = &Qs[i0 * QK_STRIDE]; const float* q1 = q0 + QK_STRIDE;
        const float* k0 = &Ks[j0 * QK_STRIDE]; const float* k1 = k0 + QK_STRIDE;
        float a00 = 0.f, a01 = 0.f, a10 = 0.f, a11 = 0.f;
#pragma unroll
        for (int e = 0; e < 64; e++) {
            float qa = q0[e], qb = q1[e], ka = k0[e], kb = k1[e];
            a00 = fmaf(qa, ka, a00); a01 = fmaf(qa, kb, a01);
            a10 = fmaf(qb, ka, a10); a11 = fmaf(qb, kb, a11);
        }
        P[i0 * 40 + j0]           = a00;
        P[i0 * 40 + j0 + 1]       = a01;
        P[(i0 + 1) * 40 + j0]     = a10;
        P[(i0 + 1) * 40 + j0 + 1] = a11;
    }
    __syncthreads();

    if (t < 36) {
        float mx = -1e30f;
        for (int j = 0; j < 36; j++) mx = fmaxf(mx, P[t * 40 + j]);
        float sum = 0.f;
        for (int j = 0; j < 36; j++) {
            float ex = expf(P[t * 40 + j] - mx);
            P[t * 40 + j] = ex;
            sum += ex;
        }
        float inv = 1.f / sum;
        for (int j = 0; j < 36; j++) P[t * 40 + j] *= inv;
    }
    __syncthreads();

    float* zr = g_z + (size_t)bc * 36 * 768 + h * 64;
    for (int vt = t; vt < 576; vt += 256) {      // 18 rows x 32 col pairs
        int i0 = (vt / 32) * 2, e0 = (vt % 32) * 2;
        const float* p0 = &P[i0 * 40]; const float* p1 = p0 + 40;
        float a00 = 0.f, a01 = 0.f, a10 = 0.f, a11 = 0.f;
#pragma unroll
        for (int j = 0; j < 36; j++) {
            float2 v = *(const float2*)&Vs[j * V_STRIDE + e0];
            float w0 = p0[j], w1 = p1[j];
            a00 = fmaf(w0, v.x, a00); a01 = fmaf(w0, v.y, a01);
            a10 = fmaf(w1, v.x, a10); a11 = fmaf(w1, v.y, a11);
        }
        float* z0 = zr + (size_t)i0 * 768 + e0;
        z0[0]   += a00; z0[1]   += a01;
        z0[768] += a10; z0[769] += a11;
    }
}

// ------------------------------- launch ------------------------------------
extern "C" void kernel_launch(void* const* d_in, const int* in_sizes, int n_in,
                              void* d_out, int out_size)
{
    (void)in_sizes; (void)n_in; (void)out_size;
    const float* batch = (const float*)d_in[0];
    const float* Wp    = (const float*)d_in[1];
    const float* bp    = (const float*)d_in[2];
    const float* pos   = (const float*)d_in[3];
    const float* ln1g  = (const float*)d_in[4];
    const float* ln1b  = (const float*)d_in[5];
    const float* Wq    = (const float*)d_in[6];
    const float* bq    = (const float*)d_in[7];
    const float* Wk    = (const float*)d_in[8];
    const float* bk    = (const float*)d_in[9];
    const float* Wv    = (const float*)d_in[10];
    const float* bv    = (const float*)d_in[11];
    const float* ln2g  = (const float*)d_in[12];
    const float* ln2b  = (const float*)d_in[13];
    const float* W1    = (const float*)d_in[14];
    const float* b1    = (const float*)d_in[15];
    const float* W2    = (const float*)d_in[16];
    const float* b2    = (const float*)d_in[17];
    const float* Wout  = (const float*)d_in[18];
    const float* bout  = (const float*)d_in[19];

    float *zp, *qkvp, *bpp;
    uint16_t *hh, *hl, *mh, *w1p, *w2p, *wqp, *wop;
    cudaGetSymbolAddress((void**)&zp,   g_z);
    cudaGetSymbolAddress((void**)&qkvp, g_qkv);
    cudaGetSymbolAddress((void**)&bpp,  g_bp);
    cudaGetSymbolAddress((void**)&hh,   g_hh);
    cudaGetSymbolAddress((void**)&hl,   g_hl);
    cudaGetSymbolAddress((void**)&mh,   g_mh);
    cudaGetSymbolAddress((void**)&w1p,  g_w1);
    cudaGetSymbolAddress((void**)&w2p,  g_w2);
    cudaGetSymbolAddress((void**)&wqp,  g_wq);
    cudaGetSymbolAddress((void**)&wop,  g_wo);

    cudaFuncSetAttribute(gemm_fp16<false,false,true ,false,true >,
                         cudaFuncAttributeMaxDynamicSharedMemorySize, SMEM_BYTES);
    cudaFuncSetAttribute(gemm_fp16<true ,false,false,true ,false>,
                         cudaFuncAttributeMaxDynamicSharedMemorySize, SMEM_BYTES);
    cudaFuncSetAttribute(gemm_fp16<false,true ,false,false,true >,
                         cudaFuncAttributeMaxDynamicSharedMemorySize, SMEM_BYTES);
    cudaFuncSetAttribute(gemm_fp16<false,false,false,false,true >,
                         cudaFuncAttributeMaxDynamicSharedMemorySize, SMEM_BYTES);

    const int nW1 = NL * DMLP * DD;
    conv_f16<<<(nW1 + 255) / 256, 256>>>(W1, w1p, nW1);
    conv_f16<<<(nW1 + 255) / 256, 256>>>(W2, w2p, nW1);
    conv_f16<<<(DOUT * DD + 255) / 256, 256>>>(Wout, wop, DOUT * DD);
    pack_qkv_w<<<(NL * NQKV * 128 + 255) / 256, 256>>>(Wq, Wk, Wv);
    pack_qkv_b<<<(NL * NQKV + 255) / 256, 256>>>(bq, bk, bv);

    patch_embed_kernel<<<dim3(6, NBC), 128>>>(batch, Wp, bp, pos);

    const dim3 gQ(NQKV / BN, NT / BM);
    const dim3 g1(DMLP / BN, NT / BM);
    const dim3 g2(DD / BN, NT / BM);
    const dim3 gO(DOUT / BN, NT / BM);

    for (int l = 0; l < NL; l++) {
        ln_split<<<NT, 256>>>(zp, hh, hl, ln1g + l * 768, ln1b + l * 768);
        gemm_fp16<false,false,true,false,true><<<gQ, 256, SMEM_BYTES>>>(
            hh, 768, wqp + (size_t)l * NQKV * 128, 128,
            bpp + l * NQKV, nullptr, nullptr, qkvp, nullptr, NQKV, 128);
        attn_kernel<<<dim3(NBC, NH), 256>>>();
        ln_split<<<NT, 256>>>(zp, hh, hl, ln2g + l * 768, ln2b + l * 768);
        gemm_fp16<true,false,false,true,false><<<g1, 256, SMEM_BYTES>>>(
            hh, 768, w1p + (size_t)l * DMLP * DD, 768,
            b1 + l * DMLP, nullptr, nullptr, nullptr, mh, DMLP, 768);
        gemm_fp16<false,true,false,false,true><<<g2, 256, SMEM_BYTES>>>(
            mh, 1536, w2p + (size_t)l * DD * DMLP, 1536,
            b2 + l * 768, hh, hl, zp, nullptr, DD, 1536);
    }

    // final z -> fp16, then out projection
    conv_f16<<<(NT * DD + 255) / 256, 256>>>(zp, hh, NT * DD);
    gemm_fp16<false,false,false,false,true><<<gO, 256, SMEM_BYTES>>>(
        hh, 768, wop, 768, bout, nullptr, nullptr,
        (float*)d_out, nullptr, DOUT, 768);
}

// round 17
// speedup vs baseline: 3.7134x; 1.0890x over previous
#include <cuda_runtime.h>
#include <cuda_fp16.h>
#include <cstdint>

// ---------------------------------------------------------------------------
// FeatureExtractorViT (B=512,C=3,IMG=36,PS=6,S=36,D=768,H=12,HD=64,L=4,OUT=256)
// NT = 55296 tokens.  GEMMs via mma.sync fp16 (HMMA) single pass, fp32 acc
// (HMMA pipe-rate floor ~15.5 cyc/MMA/SMSP measured).  qkv + attn in fp16
// storage / half2 smem; residual stream fp32.
// ---------------------------------------------------------------------------

#define NT    55296
#define DD    768
#define NBC   1536
#define NH    12
#define NL    4
#define DOUT  256
#define DMLP  1536
#define NQKV  2304

// GEMM tiling
#define BM 256
#define BN 128
#define BK 32               // fp32 k per chunk
#define KSA 40              // A smem row stride (fp16), conflict-free (80B)
#define KSB 40              // B smem row stride
#define ASZ (BM * KSA * 2)  // 20480 B per A buffer
#define BSZ (BN * KSB * 2)  // 10240 B per B buffer
#define SMEM_BYTES (2 * ASZ + 2 * BSZ)   // 61440

// ---------------- scratch (device globals; no runtime alloc) ---------------
static __device__ float    g_z[(size_t)NT * DD];        // residual stream (fp32)
static __device__ uint16_t g_qkv[(size_t)NT * NQKV];    // q|k|v (fp16)
static __device__ uint16_t g_hh[(size_t)NT * DD];       // LN out hi (fp16)
static __device__ uint16_t g_hl[(size_t)NT * DD];       // LN out lo (LN2 only)
static __device__ uint16_t g_mh[(size_t)NT * DMLP];     // MLP hidden (fp16)
static __device__ uint16_t g_w1[(size_t)NL * DMLP * DD];
static __device__ uint16_t g_w2[(size_t)NL * DD * DMLP];
static __device__ uint16_t g_wq[(size_t)NL * NQKV * 128];
static __device__ uint16_t g_wo[(size_t)DOUT * DD];
static __device__ float    g_bp[(size_t)NL * NQKV];

// ---------------------------- helpers --------------------------------------
__device__ __forceinline__ uint32_t smem_u32(const void* p) {
    uint32_t a;
    asm("{ .reg .u64 t; cvta.to.shared.u64 t, %1; cvt.u32.u64 %0, t; }"
        : "=r"(a) : "l"(p));
    return a;
}
__device__ __forceinline__ float h2f(uint16_t b) {
    return __half2float(__ushort_as_half(b));
}
__device__ __forceinline__ void split1(float x, uint16_t& h, uint16_t& l) {
    __half hb = __float2half_rn(x);
    h = __half_as_ushort(hb);
    l = __half_as_ushort(__float2half_rn(x - __half2float(hb)));
}
__device__ __forceinline__ void mma16816(float& d0, float& d1, float& d2, float& d3,
                                         uint32_t a0, uint32_t a1, uint32_t a2,
                                         uint32_t a3, uint32_t b0, uint32_t b1) {
    asm("mma.sync.aligned.m16n8k16.row.col.f32.f16.f16.f32 "
        "{%0,%1,%2,%3}, {%4,%5,%6,%7}, {%8,%9}, {%0,%1,%2,%3};"
        : "+f"(d0), "+f"(d1), "+f"(d2), "+f"(d3)
        : "r"(a0), "r"(a1), "r"(a2), "r"(a3), "r"(b0), "r"(b1));
}
__device__ __forceinline__ void ldsm4(uint32_t& r0, uint32_t& r1, uint32_t& r2,
                                      uint32_t& r3, uint32_t addr) {
    asm volatile("ldmatrix.sync.aligned.m8n8.x4.shared.b16 {%0,%1,%2,%3}, [%4];"
                 : "=r"(r0), "=r"(r1), "=r"(r2), "=r"(r3) : "r"(addr));
}
#define CP16(dst, src) \
    asm volatile("cp.async.ca.shared.global [%0], [%1], 16;" :: "r"(dst), "l"(src))
#define CP_COMMIT() asm volatile("cp.async.commit_group;" ::: "memory")
#define CP_WAIT(n)  asm volatile("cp.async.wait_group %0;" :: "n"(n) : "memory")

// ---------------------- GEMM: C = A @ B^T (+bias,+relu,+res) ---------------
// A: [M,K] fp16 (lda);  B: [N,K] fp16 (ldb).  fp32 accumulate.
// Tile 256x128, 8 warps (4x2), warp 64x64.  Double-buffered cp.async.
template <bool RELU, bool RES, bool QKV, bool OH16, bool OF32>
__global__ void __launch_bounds__(256)
gemm_fp16(const uint16_t* __restrict__ Aw, int lda,
          const uint16_t* __restrict__ Bw, int ldb,
          const float* __restrict__ bias,
          const uint16_t* __restrict__ reshi, const uint16_t* __restrict__ reslo,
          float* __restrict__ C, uint16_t* __restrict__ Ch,
          int N, int K)
{
    extern __shared__ __align__(16) unsigned char dsm[];
    const int t = threadIdx.x;
    const int lane = t & 31, wid = t >> 5;
    const int wm = wid & 3, wn = wid >> 2;           // 4x2 warp grid
    const int n0 = blockIdx.x * BN;
    const int m0 = blockIdx.y * BM;
    const int acol0 = QKV ? (n0 % 768) : 0;          // QKV K-window
    const uint32_t sA0 = smem_u32(dsm);
    const uint32_t sB0 = sA0 + 2 * ASZ;

    float acc[4][8][4];
#pragma unroll
    for (int i = 0; i < 4; i++)
#pragma unroll
        for (int j = 0; j < 8; j++)
#pragma unroll
            for (int q = 0; q < 4; q++) acc[i][j][q] = 0.f;

    auto load_chunk = [&](int ck, int buf) {
        const int kb = acol0 + ck * BK;
#pragma unroll
        for (int i = 0; i < 4; i++) {                 // A: 1024 16B segs
            int seg = t + i * 256;
            int row = seg >> 2, part = seg & 3;
            int kk = part * 8;
            const uint16_t* src = Aw + (size_t)(m0 + row) * lda + kb + kk;
            uint32_t dst = sA0 + buf * ASZ + (uint32_t)(row * KSA + kk) * 2;
            CP16(dst, src);
        }
        const int kb2 = ck * BK;
#pragma unroll
        for (int i = 0; i < 2; i++) {                 // B: 512 16B segs
            int seg = t + i * 256;
            int row = seg >> 2, part = seg & 3;
            int kk = part * 8;
            const uint16_t* src = Bw + (size_t)(n0 + row) * ldb + kb2 + kk;
            uint32_t dst = sB0 + buf * BSZ + (uint32_t)(row * KSB + kk) * 2;
            CP16(dst, src);
        }
    };

    // ldmatrix per-lane addresses.
    const int aRow = (lane & 7) + ((lane >> 3) & 1) * 8;
    const int aCol = (lane >> 4) * 8;
    const uint32_t aAddr = sA0 + (uint32_t)((wm * 64 + aRow) * KSA + aCol) * 2;
    const int bRow = (lane & 7) + (lane >> 4) * 8;
    const int bCol = ((lane >> 3) & 1) * 8;
    const uint32_t bAddr = sB0 + (uint32_t)((wn * 64 + bRow) * KSB + bCol) * 2;

    const int nck = K >> 5;
    load_chunk(0, 0); CP_COMMIT();

    for (int ck = 0; ck < nck; ck++) {
        const int buf = ck & 1;
        if (ck + 1 < nck) { load_chunk(ck + 1, buf ^ 1); CP_COMMIT(); CP_WAIT(1); }
        else              { CP_WAIT(0); }
        __syncthreads();
        const uint32_t aB = aAddr + buf * ASZ;
        const uint32_t bB = bAddr + buf * BSZ;
#pragma unroll
        for (int ko = 0; ko < 32; ko += 16) {
            uint32_t aa[4][4], bb[4][4];
#pragma unroll
            for (int mt = 0; mt < 4; mt++)
                ldsm4(aa[mt][0], aa[mt][1], aa[mt][2], aa[mt][3],
                      aB + (uint32_t)(mt * 16 * KSA + ko) * 2);
#pragma unroll
            for (int p = 0; p < 4; p++)        // B (2 n-tiles per x4)
                ldsm4(bb[p][0], bb[p][1], bb[p][2], bb[p][3],
                      bB + (uint32_t)(p * 16 * KSB + ko) * 2);
#pragma unroll
            for (int mt = 0; mt < 4; mt++)
#pragma unroll
                for (int p = 0; p < 4; p++) {
                    mma16816(acc[mt][2*p][0], acc[mt][2*p][1], acc[mt][2*p][2], acc[mt][2*p][3],
                             aa[mt][0], aa[mt][1], aa[mt][2], aa[mt][3], bb[p][0], bb[p][1]);
                    mma16816(acc[mt][2*p+1][0], acc[mt][2*p+1][1], acc[mt][2*p+1][2], acc[mt][2*p+1][3],
                             aa[mt][0], aa[mt][1], aa[mt][2], aa[mt][3], bb[p][2], bb[p][3]);
                }
        }
        __syncthreads();
    }

    // epilogue
#pragma unroll
    for (int nt = 0; nt < 8; nt++) {
        const int c0 = n0 + wn * 64 + nt * 8 + (lane & 3) * 2;
        const float b0 = bias[c0], b1v = bias[c0 + 1];
#pragma unroll
        for (int mt = 0; mt < 4; mt++) {
            const int r0 = m0 + wm * 64 + mt * 16 + (lane >> 2);
#pragma unroll
            for (int half = 0; half < 2; half++) {
                const int r = r0 + half * 8;
                float v0 = acc[mt][nt][half * 2 + 0] + b0;
                float v1 = acc[mt][nt][half * 2 + 1] + b1v;
                if (RELU) { v0 = fmaxf(v0, 0.f); v1 = fmaxf(v1, 0.f); }
                const size_t off = (size_t)r * N + c0;
                if (RES) {
                    v0 += h2f(reshi[off])     + h2f(reslo[off]);
                    v1 += h2f(reshi[off + 1]) + h2f(reslo[off + 1]);
                }
                if (OF32) {
                    float2 o; o.x = v0; o.y = v1;
                    *(float2*)(C + off) = o;
                }
                if (OH16) {
                    uint32_t h0 = __half_as_ushort(__float2half_rn(v0));
                    uint32_t h1 = __half_as_ushort(__float2half_rn(v1));
                    *(uint32_t*)(Ch + off) = (h1 << 16) | h0;
                }
            }
        }
    }
}

// --------------------- weight conversion / packing -------------------------
__global__ void conv_f16(const float* __restrict__ src, uint16_t* __restrict__ dst,
                         int n)
{
    int i = blockIdx.x * 256 + threadIdx.x;
    if (i < n) dst[i] = __half_as_ushort(__float2half_rn(src[i]));
}

__global__ void pack_qkv_w(const float* __restrict__ Wq, const float* __restrict__ Wk,
                           const float* __restrict__ Wv)
{
    int idx = blockIdx.x * 256 + threadIdx.x;
    if (idx >= NL * NQKV * 128) return;
    int l = idx / (NQKV * 128);
    int rem = idx % (NQKV * 128);
    int c = rem / 128, kk = rem % 128;
    int mat = c / 768, cw = c % 768;
    int h = cw / 64, e = cw % 64;
    int kwin = (cw / 128) * 128;
    int d = kwin + kk - h * 64;
    float val = 0.f;
    if (d >= 0 && d < 64) {
        const float* W = (mat == 0) ? Wq : (mat == 1 ? Wk : Wv);
        val = W[(((size_t)l * NH + h) * 64 + e) * 64 + d];
    }
    g_wq[idx] = __half_as_ushort(__float2half_rn(val));
}
__global__ void pack_qkv_b(const float* __restrict__ bq, const float* __restrict__ bk,
                           const float* __restrict__ bv)
{
    int idx = blockIdx.x * 256 + threadIdx.x;
    if (idx >= NL * NQKV) return;
    int l = idx / NQKV, c = idx % NQKV;
    int mat = c / 768, cw = c % 768;
    int h = cw / 64, e = cw % 64;
    const float* b = (mat == 0) ? bq : (mat == 1 ? bk : bv);
    g_bp[idx] = b[((size_t)l * NH + h) * 64 + e];
}

// ---------------------------- patch embed ----------------------------------
__global__ void patch_embed_kernel(const float* __restrict__ batch,
                                   const float* __restrict__ Wp,
                                   const float* __restrict__ bp,
                                   const float* __restrict__ pos)
{
    __shared__ float px[36 * 36];
    __shared__ float Ws[128 * 36];
    const int bc = blockIdx.y, d0 = blockIdx.x * 128, t = threadIdx.x;
    const float* img = batch + bc * 1296;
    for (int e = t; e < 1296; e += 128) {
        int row = e / 36, col = e - row * 36;
        int s = (row / 6) * 6 + (col / 6);
        int p = (row % 6) * 6 + (col % 6);
        px[s * 36 + p] = img[e];
    }
    for (int i = t; i < 128 * 36; i += 128) Ws[i] = Wp[d0 * 36 + i];
    __syncthreads();
    const int d = d0 + t;
    float w[36];
#pragma unroll
    for (int p = 0; p < 36; p++) w[p] = Ws[t * 36 + p];
    const float bias = bp[d];
    for (int s = 0; s < 36; s++) {
        float acc = bias + pos[s * 768 + d];
        const float* pr = &px[s * 36];
#pragma unroll
        for (int p = 0; p < 36; p++) acc = fmaf(pr[p], w[p], acc);
        g_z[(size_t)(bc * 36 + s) * 768 + d] = acc;
    }
}

// ------------------------ LayerNorm -> fp16 hi(/lo) ------------------------
__global__ void ln_split(const float* __restrict__ in, uint16_t* __restrict__ hi,
                         uint16_t* __restrict__ lo, const float* __restrict__ gamma,
                         const float* __restrict__ beta)
{
    const int row = blockIdx.x;
    const float* x = in + (size_t)row * 768;
    const int t = threadIdx.x;
    float v0 = x[t], v1 = x[t + 256], v2 = x[t + 512];
    float s = v0 + v1 + v2;
    float q = v0 * v0 + v1 * v1 + v2 * v2;
#pragma unroll
    for (int o = 16; o > 0; o >>= 1) {
        s += __shfl_xor_sync(0xffffffffu, s, o);
        q += __shfl_xor_sync(0xffffffffu, q, o);
    }
    __shared__ float rs[8], rq[8];
    __shared__ float smean, srstd;
    if ((t & 31) == 0) { rs[t >> 5] = s; rq[t >> 5] = q; }
    __syncthreads();
    if (t == 0) {
        float S = 0.f, Q = 0.f;
#pragma unroll
        for (int i = 0; i < 8; i++) { S += rs[i]; Q += rq[i]; }
        float m = S * (1.0f / 768.0f);
        float var = Q * (1.0f / 768.0f) - m * m;
        smean = m; srstd = rsqrtf(var + 1e-5f);
    }
    __syncthreads();
    const float m = smean, r = srstd;
    const size_t base = (size_t)row * 768;
    float y0 = (v0 - m) * r * gamma[t]       + beta[t];
    float y1 = (v1 - m) * r * gamma[t + 256] + beta[t + 256];
    float y2 = (v2 - m) * r * gamma[t + 512] + beta[t + 512];
    uint16_t h, l;
    if (lo) {
        split1(y0, h, l); hi[base + t]       = h; lo[base + t]       = l;
        split1(y1, h, l); hi[base + t + 256] = h; lo[base + t + 256] = l;
        split1(y2, h, l); hi[base + t + 512] = h; lo[base + t + 512] = l;
    } else {
        hi[base + t]       = __half_as_ushort(__float2half_rn(y0));
        hi[base + t + 256] = __half_as_ushort(__float2half_rn(y1));
        hi[base + t + 512] = __half_as_ushort(__float2half_rn(y2));
    }
}

// ---------------------------- attention ------------------------------------
// qkv stored fp16.  Smem tiles kept as packed half2 words (halves LDS bytes);
// scores, softmax and accumulation in fp32.  1/sqrt(64) folded into P store.
#define QKW 34    // uint32 words per row (32 data + 2 pad)
__global__ void __launch_bounds__(256) attn_kernel()
{
    __shared__ uint32_t Qs[36 * QKW], Ks[36 * QKW], Vs[36 * QKW];
    __shared__ float P[36 * 40];
    const int bc = blockIdx.x, h = blockIdx.y, t = threadIdx.x;
    const uint32_t* qkv32 = (const uint32_t*)g_qkv;
    const size_t qb = (size_t)bc * 36 * (NQKV / 2) + h * 32;

    for (int idx = t; idx < 1152; idx += 256) {
        int s = idx >> 5, e2 = idx & 31;
        size_t g = qb + (size_t)s * (NQKV / 2) + e2;
        Qs[s * QKW + e2] = qkv32[g];
        Ks[s * QKW + e2] = qkv32[g + 384];    // +768 halfs
        Vs[s * QKW + e2] = qkv32[g + 768];    // +1536 halfs
    }
    __syncthreads();

    for (int vt = t; vt < 324; vt += 256) {      // 18x18 of 2x2 score tiles
        int i0 = (vt / 18) * 2, j0 = (vt % 18) * 2;
        const uint32_t* q0 = &Qs[i0 * QKW]; const uint32_t* q1 = q0 + QKW;
        const uint32_t* k0 = &Ks[j0 * QKW]; const uint32_t* k1 = k0 + QKW;
        float a00 = 0.f, a01 = 0.f, a10 = 0.f, a11 = 0.f;
#pragma unroll
        for (int e2 = 0; e2 < 32; e2++) {
            float2 qa = __half22float2(*(const __half2*)&q0[e2]);
            float2 qb2 = __half22float2(*(const __half2*)&q1[e2]);
            float2 ka = __half22float2(*(const __half2*)&k0[e2]);
            float2 kb = __half22float2(*(const __half2*)&k1[e2]);
            a00 = fmaf(qa.x, ka.x, a00); a00 = fmaf(qa.y, ka.y, a00);
            a01 = fmaf(qa.x, kb.x, a01); a01 = fmaf(qa.y, kb.y, a01);
            a10 = fmaf(qb2.x, ka.x, a10); a10 = fmaf(qb2.y, ka.y, a10);
            a11 = fmaf(qb2.x, kb.x, a11); a11 = fmaf(qb2.y, kb.y, a11);
        }
        P[i0 * 40 + j0]           = a00 * 0.125f;
        P[i0 * 40 + j0 + 1]       = a01 * 0.125f;
        P[(i0 + 1) * 40 + j0]     = a10 * 0.125f;
        P[(i0 + 1) * 40 + j0 + 1] = a11 * 0.125f;
    }
    __syncthreads();

    if (t < 36) {
        float mx = -1e30f;
        for (int j = 0; j < 36; j++) mx = fmaxf(mx, P[t * 40 + j]);
        float sum = 0.f;
        for (int j = 0; j < 36; j++) {
            float ex = expf(P[t * 40 + j] - mx);
            P[t * 40 + j] = ex;
            sum += ex;
        }
        float inv = 1.f / sum;
        for (int j = 0; j < 36; j++) P[t * 40 + j] *= inv;
    }
    __syncthreads();

    float* zr = g_z + (size_t)bc * 36 * 768 + h * 64;
    for (int vt = t; vt < 576; vt += 256) {      // 18 rows x 32 col pairs
        int i0 = (vt / 32) * 2, e2v = vt & 31;
        const float* p0 = &P[i0 * 40]; const float* p1 = p0 + 40;
        float a00 = 0.f, a01 = 0.f, a10 = 0.f, a11 = 0.f;
#pragma unroll
        for (int j = 0; j < 36; j++) {
            float2 v = __half22float2(*(const __half2*)&Vs[j * QKW + e2v]);
            float w0 = p0[j], w1 = p1[j];
            a00 = fmaf(w0, v.x, a00); a01 = fmaf(w0, v.y, a01);
            a10 = fmaf(w1, v.x, a10); a11 = fmaf(w1, v.y, a11);
        }
        float* z0 = zr + (size_t)i0 * 768 + e2v * 2;
        z0[0]   += a00; z0[1]   += a01;
        z0[768] += a10; z0[769] += a11;
    }
}

// ------------------------------- launch ------------------------------------
extern "C" void kernel_launch(void* const* d_in, const int* in_sizes, int n_in,
                              void* d_out, int out_size)
{
    (void)in_sizes; (void)n_in; (void)out_size;
    const float* batch = (const float*)d_in[0];
    const float* Wp    = (const float*)d_in[1];
    const float* bp    = (const float*)d_in[2];
    const float* pos   = (const float*)d_in[3];
    const float* ln1g  = (const float*)d_in[4];
    const float* ln1b  = (const float*)d_in[5];
    const float* Wq    = (const float*)d_in[6];
    const float* bq    = (const float*)d_in[7];
    const float* Wk    = (const float*)d_in[8];
    const float* bk    = (const float*)d_in[9];
    const float* Wv    = (const float*)d_in[10];
    const float* bv    = (const float*)d_in[11];
    const float* ln2g  = (const float*)d_in[12];
    const float* ln2b  = (const float*)d_in[13];
    const float* W1    = (const float*)d_in[14];
    const float* b1    = (const float*)d_in[15];
    const float* W2    = (const float*)d_in[16];
    const float* b2    = (const float*)d_in[17];
    const float* Wout  = (const float*)d_in[18];
    const float* bout  = (const float*)d_in[19];

    float *zp, *bpp;
    uint16_t *qkvp, *hh, *hl, *mh, *w1p, *w2p, *wqp, *wop;
    cudaGetSymbolAddress((void**)&zp,   g_z);
    cudaGetSymbolAddress((void**)&qkvp, g_qkv);
    cudaGetSymbolAddress((void**)&bpp,  g_bp);
    cudaGetSymbolAddress((void**)&hh,   g_hh);
    cudaGetSymbolAddress((void**)&hl,   g_hl);
    cudaGetSymbolAddress((void**)&mh,   g_mh);
    cudaGetSymbolAddress((void**)&w1p,  g_w1);
    cudaGetSymbolAddress((void**)&w2p,  g_w2);
    cudaGetSymbolAddress((void**)&wqp,  g_wq);
    cudaGetSymbolAddress((void**)&wop,  g_wo);

    cudaFuncSetAttribute(gemm_fp16<false,false,true ,true ,false>,
                         cudaFuncAttributeMaxDynamicSharedMemorySize, SMEM_BYTES);
    cudaFuncSetAttribute(gemm_fp16<true ,false,false,true ,false>,
                         cudaFuncAttributeMaxDynamicSharedMemorySize, SMEM_BYTES);
    cudaFuncSetAttribute(gemm_fp16<false,true ,false,false,true >,
                         cudaFuncAttributeMaxDynamicSharedMemorySize, SMEM_BYTES);
    cudaFuncSetAttribute(gemm_fp16<false,false,false,false,true >,
                         cudaFuncAttributeMaxDynamicSharedMemorySize, SMEM_BYTES);

    const int nW1 = NL * DMLP * DD;
    conv_f16<<<(nW1 + 255) / 256, 256>>>(W1, w1p, nW1);
    conv_f16<<<(nW1 + 255) / 256, 256>>>(W2, w2p, nW1);
    conv_f16<<<(DOUT * DD + 255) / 256, 256>>>(Wout, wop, DOUT * DD);
    pack_qkv_w<<<(NL * NQKV * 128 + 255) / 256, 256>>>(Wq, Wk, Wv);
    pack_qkv_b<<<(NL * NQKV + 255) / 256, 256>>>(bq, bk, bv);

    patch_embed_kernel<<<dim3(6, NBC), 128>>>(batch, Wp, bp, pos);

    const dim3 gQ(NQKV / BN, NT / BM);
    const dim3 g1(DMLP / BN, NT / BM);
    const dim3 g2(DD / BN, NT / BM);
    const dim3 gO(DOUT / BN, NT / BM);

    for (int l = 0; l < NL; l++) {
        ln_split<<<NT, 256>>>(zp, hh, nullptr, ln1g + l * 768, ln1b + l * 768);
        gemm_fp16<false,false,true,true,false><<<gQ, 256, SMEM_BYTES>>>(
            hh, 768, wqp + (size_t)l * NQKV * 128, 128,
            bpp + l * NQKV, nullptr, nullptr, nullptr, qkvp, NQKV, 128);
        attn_kernel<<<dim3(NBC, NH), 256>>>();
        ln_split<<<NT, 256>>>(zp, hh, hl, ln2g + l * 768, ln2b + l * 768);
        gemm_fp16<true,false,false,true,false><<<g1, 256, SMEM_BYTES>>>(
            hh, 768, w1p + (size_t)l * DMLP * DD, 768,
            b1 + l * DMLP, nullptr, nullptr, nullptr, mh, DMLP, 768);
        gemm_fp16<false,true,false,false,true><<<g2, 256, SMEM_BYTES>>>(
            mh, 1536, w2p + (size_t)l * DD * DMLP, 1536,
            b2 + l * 768, hh, hl, zp, nullptr, DD, 1536);
    }

    // final z -> fp16, then out projection
    conv_f16<<<(NT * DD + 255) / 256, 256>>>(zp, hh, NT * DD);
    gemm_fp16<false,false,false,false,true><<<gO, 256, SMEM_BYTES>>>(
        hh, 768, wop, 768, bout, nullptr, nullptr,
        (float*)d_out, nullptr, DOUT, 768);
}